// round 8
// baseline (speedup 1.0000x reference)
#include <cuda_runtime.h>
#include <cuda_bf16.h>
#include <cstdint>

#define D 128
#define TILE_ROWS 128
#define FUSED_THREADS 512
#define ROWS_PER_WARP 8

typedef unsigned long long ull;

// -------- scratch (no cudaMalloc allowed) --------
#define MAX_NODES 100000
#define MAX_EDGES 1600000
__device__ float g_xA[(size_t)MAX_NODES * D];
__device__ float g_xB[(size_t)MAX_NODES * D];
__device__ int   g_counts[MAX_NODES];
__device__ int   g_offs[MAX_NODES + 1];
__device__ int   g_cursor[MAX_NODES];
__device__ int   g_csr_src[MAX_EDGES];

// -------- packed fp32x2 helpers (Blackwell FFMA2) --------
__device__ __forceinline__ ull pack2(float lo, float hi) {
    ull r; asm("mov.b64 %0, {%1,%2};" : "=l"(r) : "f"(lo), "f"(hi)); return r;
}
__device__ __forceinline__ void fma2(ull &d, ull a, ull b) {
    asm("fma.rn.f32x2 %0, %1, %2, %0;" : "+l"(d) : "l"(a), "l"(b));
}
__device__ __forceinline__ float2 unpack2(ull v) {
    float2 f; asm("mov.b64 {%0,%1}, %2;" : "=f"(f.x), "=f"(f.y) : "l"(v)); return f;
}

// ================= CSR build =================
__global__ void hist_kernel(const int* __restrict__ ei, int E, int* __restrict__ counts) {
    int e = blockIdx.x * blockDim.x + threadIdx.x;
    if (e < E) atomicAdd(&counts[ei[(size_t)E + e]], 1);
}

__global__ void scan_kernel(const int* __restrict__ counts, int N, int E,
                            int* __restrict__ offs, int* __restrict__ cursor) {
    __shared__ int sm[1024];
    const int tid = threadIdx.x;
    const int chunk = (N + 1023) / 1024;
    const int lo = tid * chunk;
    const int hi = min(lo + chunk, N);
    int s = 0;
    for (int i = lo; i < hi; i++) s += counts[i];
    sm[tid] = s;
    __syncthreads();
    for (int off = 1; off < 1024; off <<= 1) {
        int t = (tid >= off) ? sm[tid - off] : 0;
        __syncthreads();
        sm[tid] += t;
        __syncthreads();
    }
    int run = sm[tid] - s;
    for (int i = lo; i < hi; i++) {
        int c = counts[i];
        offs[i] = run; cursor[i] = run;
        run += c;
    }
    if (tid == 0) offs[N] = E;
}

__global__ void fill_kernel(const int* __restrict__ ei, int E,
                            int* __restrict__ cursor, int* __restrict__ csr_src) {
    int e = blockIdx.x * blockDim.x + threadIdx.x;
    if (e < E) {
        int d = ei[(size_t)E + e];
        int pos = atomicAdd(&cursor[d], 1);
        csr_src[pos] = ei[e];
    }
}

// ================= fused layer: gather + GIN MLP (warp-autonomous, 2D lane tile) =================
// Warp owns 8 rows (private SMEM region). Lane grid 4x8: rg=lane>>3, cg=lane&7.
// Lane computes rows {2rg, 2rg+1} x cols [16cg, 16cg+16).
// rows swizzle: element (r,k) at r*128 + 4*((k>>2) ^ r) + (k&3)    (r = local 0..7)
//   -> v LDS.128: 4 distinct addrs (rg), 8-lane broadcast, distinct banks: 1 wf.
// W swizzle:    element (c,k) at c*128 + 4*((k>>2) ^ ((c>>2)&31)) + (k&3)
//   -> w LDS.128: 8 distinct addrs (cg), 4-lane broadcast, distinct banks: 1 wf.
// h overwrites rows in place (warp-private; syncwarp separates read/write phases).
__global__ void __launch_bounds__(FUSED_THREADS, 1) fused_layer_kernel(
    const float4* __restrict__ x4,
    const float* __restrict__ W1, const float* __restrict__ b1,
    const float* __restrict__ W2, const float* __restrict__ b2,
    const int* __restrict__ offs, const int* __restrict__ csr,
    float* __restrict__ xout, int n, int ntiles)
{
    extern __shared__ float smem[];
    float* W1s  = smem;                 // 16384 floats
    float* W2s  = W1s + 16384;          // 16384
    float* rows = W2s + 16384;          // 16 warps * 8 rows * 128 = 16384
    float* b1s  = rows + 16384;         // 128
    float* b2s  = b1s + 128;            // 128

    const int tid  = threadIdx.x;
    const int lane = tid & 31;
    const int wid  = tid >> 5;              // warp 0..15
    const int rg   = lane >> 3;             // 0..3
    const int cg   = lane & 7;              // 0..7
    const int r0   = rg * 2;                // local rows
    const int r1   = rg * 2 + 1;
    float* rows_w  = rows + wid * (ROWS_PER_WARP * 128);   // warp-private 8x128

    // ---- stage W1^T, W2^T (XOR swizzle) + biases ----
    {
        const float4* w1g = (const float4*)W1;
        const float4* w2g = (const float4*)W2;
        for (int i = tid; i < 4096; i += FUSED_THREADS) {
            int k = i >> 5, c4 = i & 31;
            float4 a = w1g[i];
            float4 b = w2g[i];
            int kq = k >> 2, kr = k & 3;
            #pragma unroll
            for (int j = 0; j < 4; j++) {
                int c = 4 * c4 + j;
                int addr = c * 128 + 4 * (kq ^ ((c >> 2) & 31)) + kr;
                float av = (j == 0) ? a.x : (j == 1) ? a.y : (j == 2) ? a.z : a.w;
                float bv = (j == 0) ? b.x : (j == 1) ? b.y : (j == 2) ? b.z : b.w;
                W1s[addr] = av;
                W2s[addr] = bv;
            }
        }
        if (tid < 128) { b1s[tid] = b1[tid]; b2s[tid] = b2[tid]; }
    }
    __syncthreads();   // W/b visible to all warps; only block-wide sync in kernel

    for (int t = blockIdx.x; t < ntiles; t += gridDim.x) {
        const int row0 = t * TILE_ROWS;

        // ---- gather: warp fills its private rows_w[0..7], row-swizzled ----
        for (int rr = 0; rr < ROWS_PER_WARP; rr++) {
            const int row = row0 + wid * ROWS_PER_WARP + rr;
            float4 a = make_float4(0.f, 0.f, 0.f, 0.f);
            if (row < n) {
                a = x4[(size_t)row * 32 + lane];
                const int lo = offs[row];
                const int hi = offs[row + 1];
                for (int base = lo; base < hi; base += 32) {
                    int cnt = hi - base; if (cnt > 32) cnt = 32;
                    int idx = (lane < cnt) ? csr[base + lane] : 0;
                    int j = 0;
                    for (; j + 8 <= cnt; j += 8) {
                        int s0 = __shfl_sync(0xffffffffu, idx, j + 0);
                        int s1 = __shfl_sync(0xffffffffu, idx, j + 1);
                        int s2 = __shfl_sync(0xffffffffu, idx, j + 2);
                        int s3 = __shfl_sync(0xffffffffu, idx, j + 3);
                        int s4 = __shfl_sync(0xffffffffu, idx, j + 4);
                        int s5 = __shfl_sync(0xffffffffu, idx, j + 5);
                        int s6 = __shfl_sync(0xffffffffu, idx, j + 6);
                        int s7 = __shfl_sync(0xffffffffu, idx, j + 7);
                        float4 v0 = __ldg(x4 + (size_t)s0 * 32 + lane);
                        float4 v1 = __ldg(x4 + (size_t)s1 * 32 + lane);
                        float4 v2 = __ldg(x4 + (size_t)s2 * 32 + lane);
                        float4 v3 = __ldg(x4 + (size_t)s3 * 32 + lane);
                        float4 v4 = __ldg(x4 + (size_t)s4 * 32 + lane);
                        float4 v5 = __ldg(x4 + (size_t)s5 * 32 + lane);
                        float4 v6 = __ldg(x4 + (size_t)s6 * 32 + lane);
                        float4 v7 = __ldg(x4 + (size_t)s7 * 32 + lane);
                        a.x += v0.x + v1.x + v2.x + v3.x + v4.x + v5.x + v6.x + v7.x;
                        a.y += v0.y + v1.y + v2.y + v3.y + v4.y + v5.y + v6.y + v7.y;
                        a.z += v0.z + v1.z + v2.z + v3.z + v4.z + v5.z + v6.z + v7.z;
                        a.w += v0.w + v1.w + v2.w + v3.w + v4.w + v5.w + v6.w + v7.w;
                    }
                    for (; j < cnt; j++) {
                        int s = __shfl_sync(0xffffffffu, idx, j);
                        float4 v = __ldg(x4 + (size_t)s * 32 + lane);
                        a.x += v.x; a.y += v.y; a.z += v.z; a.w += v.w;
                    }
                }
            }
            // swizzled store: quad kq = lane of row rr -> chunk (lane ^ rr)
            *(float4*)(rows_w + rr * 128 + 4 * (lane ^ rr)) = a;
        }
        __syncwarp();

        // ---- GEMM1: h = relu(rows @ W1 + b1), h overwrites rows in place ----
        {
            ull acc[2][16];
            #pragma unroll
            for (int cc = 0; cc < 16; cc++) {
                float b = b1s[cg * 16 + cc];
                acc[0][cc] = pack2(b, 0.f);
                acc[1][cc] = pack2(b, 0.f);
            }
            const float* wb  = W1s + (cg * 16) * 128;
            const float* rb0 = rows_w + r0 * 128;
            const float* rb1 = rows_w + r1 * 128;
            #pragma unroll 2
            for (int kq = 0; kq < 32; kq++) {
                ulonglong2 v0 = *(const ulonglong2*)(rb0 + 4 * (kq ^ r0));
                ulonglong2 v1 = *(const ulonglong2*)(rb1 + 4 * (kq ^ r1));
                #pragma unroll
                for (int cc = 0; cc < 16; cc += 2) {
                    int cha = 4 * (kq ^ (cg * 4 + (cc >> 2)));
                    int chb = 4 * (kq ^ (cg * 4 + ((cc + 1) >> 2)));
                    ulonglong2 wa = *(const ulonglong2*)(wb + cc * 128 + cha);
                    ulonglong2 wc = *(const ulonglong2*)(wb + (cc + 1) * 128 + chb);
                    fma2(acc[0][cc],   wa.x, v0.x); fma2(acc[1][cc],   wa.x, v1.x);
                    fma2(acc[0][cc+1], wc.x, v0.x); fma2(acc[1][cc+1], wc.x, v1.x);
                    fma2(acc[0][cc],   wa.y, v0.y); fma2(acc[1][cc],   wa.y, v1.y);
                    fma2(acc[0][cc+1], wc.y, v0.y); fma2(acc[1][cc+1], wc.y, v1.y);
                }
            }
            __syncwarp();   // all lanes done reading rows before anyone overwrites
            #pragma unroll
            for (int i = 0; i < 2; i++) {
                int r = rg * 2 + i;
                #pragma unroll
                for (int q = 0; q < 4; q++) {
                    float2 p0 = unpack2(acc[i][4 * q + 0]);
                    float2 p1 = unpack2(acc[i][4 * q + 1]);
                    float2 p2 = unpack2(acc[i][4 * q + 2]);
                    float2 p3 = unpack2(acc[i][4 * q + 3]);
                    float4 h = make_float4(fmaxf(p0.x + p0.y, 0.f), fmaxf(p1.x + p1.y, 0.f),
                                           fmaxf(p2.x + p2.y, 0.f), fmaxf(p3.x + p3.y, 0.f));
                    *(float4*)(rows_w + r * 128 + 4 * ((cg * 4 + q) ^ r)) = h;
                }
            }
        }
        __syncwarp();

        // ---- GEMM2: xout = h @ W2 + b2 ----
        {
            ull acc[2][16];
            #pragma unroll
            for (int cc = 0; cc < 16; cc++) {
                float b = b2s[cg * 16 + cc];
                acc[0][cc] = pack2(b, 0.f);
                acc[1][cc] = pack2(b, 0.f);
            }
            const float* wb  = W2s + (cg * 16) * 128;
            const float* rb0 = rows_w + r0 * 128;
            const float* rb1 = rows_w + r1 * 128;
            #pragma unroll 2
            for (int kq = 0; kq < 32; kq++) {
                ulonglong2 v0 = *(const ulonglong2*)(rb0 + 4 * (kq ^ r0));
                ulonglong2 v1 = *(const ulonglong2*)(rb1 + 4 * (kq ^ r1));
                #pragma unroll
                for (int cc = 0; cc < 16; cc += 2) {
                    int cha = 4 * (kq ^ (cg * 4 + (cc >> 2)));
                    int chb = 4 * (kq ^ (cg * 4 + ((cc + 1) >> 2)));
                    ulonglong2 wa = *(const ulonglong2*)(wb + cc * 128 + cha);
                    ulonglong2 wc = *(const ulonglong2*)(wb + (cc + 1) * 128 + chb);
                    fma2(acc[0][cc],   wa.x, v0.x); fma2(acc[1][cc],   wa.x, v1.x);
                    fma2(acc[0][cc+1], wc.x, v0.x); fma2(acc[1][cc+1], wc.x, v1.x);
                    fma2(acc[0][cc],   wa.y, v0.y); fma2(acc[1][cc],   wa.y, v1.y);
                    fma2(acc[0][cc+1], wc.y, v0.y); fma2(acc[1][cc+1], wc.y, v1.y);
                }
            }
            #pragma unroll
            for (int i = 0; i < 2; i++) {
                int row = row0 + wid * ROWS_PER_WARP + rg * 2 + i;
                if (row < n) {
                    float4* orow = (float4*)(xout + (size_t)row * 128);
                    #pragma unroll
                    for (int q = 0; q < 4; q++) {
                        float2 p0 = unpack2(acc[i][4 * q + 0]);
                        float2 p1 = unpack2(acc[i][4 * q + 1]);
                        float2 p2 = unpack2(acc[i][4 * q + 2]);
                        float2 p3 = unpack2(acc[i][4 * q + 3]);
                        orow[cg * 4 + q] = make_float4(p0.x + p0.y, p1.x + p1.y,
                                                       p2.x + p2.y, p3.x + p3.y);
                    }
                }
            }
        }
        __syncwarp();   // GEMM2 reads of rows_w complete before next gather rewrites
    }
}

// ================= readout =================
__device__ __forceinline__ int lower_bound_i(const int* __restrict__ a, int lo, int hi, int v) {
    while (lo < hi) {
        int m = (lo + hi) >> 1;
        if (a[m] < v) lo = m + 1; else hi = m;
    }
    return lo;
}

__global__ void readout_kernel(float* __restrict__ out, const float* __restrict__ xf,
                               const int* __restrict__ batch, int n) {
    const int g = blockIdx.x;
    const int j = threadIdx.x;
    int lo = lower_bound_i(batch, 0, n, g);
    int hi = lower_bound_i(batch, lo, n, g + 1);
    float s0 = 0.f, s1 = 0.f, s2 = 0.f, s3 = 0.f;
    int r = lo;
    for (; r + 4 <= hi; r += 4) {
        s0 += xf[(size_t)(r + 0) * D + j];
        s1 += xf[(size_t)(r + 1) * D + j];
        s2 += xf[(size_t)(r + 2) * D + j];
        s3 += xf[(size_t)(r + 3) * D + j];
    }
    for (; r < hi; r++) s0 += xf[(size_t)r * D + j];
    out[(size_t)g * D + j] = (s0 + s1) + (s2 + s3);
}

// ================= launch =================
extern "C" void kernel_launch(void* const* d_in, const int* in_sizes, int n_in,
                              void* d_out, int out_size) {
    const float* x   = (const float*)d_in[0];
    const float* W1  = (const float*)d_in[1];
    const float* b1  = (const float*)d_in[2];
    const float* W2  = (const float*)d_in[3];
    const float* b2  = (const float*)d_in[4];
    const int* ei    = (const int*)d_in[5];
    const int* bat   = (const int*)d_in[6];
    float* out       = (float*)d_out;

    const int N = in_sizes[0] / D;
    const int E = in_sizes[5] / 2;
    const int n_layers = in_sizes[1] / (D * D);

    float *xA, *xB;
    int *counts, *offs, *cursor, *csr;
    cudaGetSymbolAddress((void**)&xA, g_xA);
    cudaGetSymbolAddress((void**)&xB, g_xB);
    cudaGetSymbolAddress((void**)&counts, g_counts);
    cudaGetSymbolAddress((void**)&offs, g_offs);
    cudaGetSymbolAddress((void**)&cursor, g_cursor);
    cudaGetSymbolAddress((void**)&csr, g_csr_src);

    const int smem_bytes = (16384 * 3 + 256) * 4;  // 197632
    cudaFuncSetAttribute(fused_layer_kernel, cudaFuncAttributeMaxDynamicSharedMemorySize, smem_bytes);

    // ---- CSR build ----
    cudaMemsetAsync(counts, 0, (size_t)N * sizeof(int), 0);
    hist_kernel<<<(E + 255) / 256, 256>>>(ei, E, counts);      // launch 1
    scan_kernel<<<1, 1024>>>(counts, N, E, offs, cursor);      // launch 2
    fill_kernel<<<(E + 255) / 256, 256>>>(ei, E, cursor, csr); // launch 3

    // ---- layers: launch 4 (profiled), 5, 6 ----
    const int ntiles = (N + TILE_ROWS - 1) / TILE_ROWS;
    const float* xin = x;
    float* bufs[2] = { xA, xB };

    for (int l = 0; l < n_layers; l++) {
        fused_layer_kernel<<<148, FUSED_THREADS, smem_bytes>>>(
            (const float4*)xin,
            W1 + (size_t)l * D * D, b1 + (size_t)l * D,
            W2 + (size_t)l * D * D, b2 + (size_t)l * D,
            offs, csr, bufs[l & 1], N, ntiles);
        xin = bufs[l & 1];
    }

    readout_kernel<<<128, D>>>(out, xin, bat, N);
}

// round 9
// speedup vs baseline: 2.8437x; 2.8437x over previous
#include <cuda_runtime.h>
#include <cuda_bf16.h>
#include <cstdint>

#define D 128
#define TILE_ROWS 128
#define FUSED_THREADS 512
#define ROWS_PER_WARP 8

typedef unsigned long long ull;

// -------- scratch (no cudaMalloc allowed) --------
#define MAX_NODES 100000
#define MAX_EDGES 1600000
__device__ float g_xA[(size_t)MAX_NODES * D];
__device__ float g_xB[(size_t)MAX_NODES * D];
__device__ int   g_counts[MAX_NODES];
__device__ int   g_offs[MAX_NODES + 1];
__device__ int   g_cursor[MAX_NODES];
__device__ int   g_csr_src[MAX_EDGES];

// -------- packed fp32x2 helpers (Blackwell FFMA2) --------
__device__ __forceinline__ ull pack2(float lo, float hi) {
    ull r; asm("mov.b64 %0, {%1,%2};" : "=l"(r) : "f"(lo), "f"(hi)); return r;
}
__device__ __forceinline__ void fma2(ull &d, ull a, ull b) {
    asm("fma.rn.f32x2 %0, %1, %2, %0;" : "+l"(d) : "l"(a), "l"(b));
}
__device__ __forceinline__ float2 unpack2(ull v) {
    float2 f; asm("mov.b64 {%0,%1}, %2;" : "=f"(f.x), "=f"(f.y) : "l"(v)); return f;
}

// ================= CSR build =================
__global__ void hist_kernel(const int* __restrict__ ei, int E, int* __restrict__ counts) {
    int e = blockIdx.x * blockDim.x + threadIdx.x;
    if (e < E) atomicAdd(&counts[ei[(size_t)E + e]], 1);
}

__global__ void scan_kernel(const int* __restrict__ counts, int N, int E,
                            int* __restrict__ offs, int* __restrict__ cursor) {
    __shared__ int sm[1024];
    const int tid = threadIdx.x;
    const int chunk = (N + 1023) / 1024;
    const int lo = tid * chunk;
    const int hi = min(lo + chunk, N);
    int s = 0;
    for (int i = lo; i < hi; i++) s += counts[i];
    sm[tid] = s;
    __syncthreads();
    for (int off = 1; off < 1024; off <<= 1) {
        int t = (tid >= off) ? sm[tid - off] : 0;
        __syncthreads();
        sm[tid] += t;
        __syncthreads();
    }
    int run = sm[tid] - s;
    for (int i = lo; i < hi; i++) {
        int c = counts[i];
        offs[i] = run; cursor[i] = run;
        run += c;
    }
    if (tid == 0) offs[N] = E;
}

__global__ void fill_kernel(const int* __restrict__ ei, int E,
                            int* __restrict__ cursor, int* __restrict__ csr_src) {
    int e = blockIdx.x * blockDim.x + threadIdx.x;
    if (e < E) {
        int d = ei[(size_t)E + e];
        int pos = atomicAdd(&cursor[d], 1);
        csr_src[pos] = ei[e];
    }
}

// ================= fused layer (R7 structure, 8 rows/warp, in-place h) =================
// R7-proven layout:
//  - W^T XOR-swizzled: element (c,k) at word c*128 + 4*((k>>2) ^ ((c>>2)&31)) + (k&3).
//    w LDS.128 chunk index = (kq ^ lane) XORs the FULL 5-bit lane -> each 8-lane
//    phase hits 8 distinct 16B chunks -> conflict-free (verified mod-32).
//  - rows plain row-major; v loads are whole-warp broadcasts (1 wf).
//  - rows/h region is warp-private -> no __syncthreads in tile loop.
// New vs R7: 8 rows/warp (W-LDS bytes per row -25%), h overwrites rows in place
// (syncwarp separates the kq-loop reads from the h stores), TILE=128.
__global__ void __launch_bounds__(FUSED_THREADS, 1) fused_layer_kernel(
    const float4* __restrict__ x4,
    const float* __restrict__ W1, const float* __restrict__ b1,
    const float* __restrict__ W2, const float* __restrict__ b2,
    const int* __restrict__ offs, const int* __restrict__ csr,
    float* __restrict__ xout, int n, int ntiles)
{
    extern __shared__ float smem[];
    float* W1s  = smem;                 // 16384 floats (transposed + swizzled)
    float* W2s  = W1s + 16384;          // 16384
    float* rows = W2s + 16384;          // 16 warps * 8 rows * 128 = 16384
    float* b1s  = rows + 16384;         // 128
    float* b2s  = b1s + 128;            // 128

    const int tid  = threadIdx.x;
    const int lane = tid & 31;
    const int wid  = tid >> 5;          // warp 0..15, owns 8 rows
    float* rows_w  = rows + wid * (ROWS_PER_WARP * 128);

    // ---- stage W1^T, W2^T with XOR swizzle + biases ----
    {
        const float4* w1g = (const float4*)W1;
        const float4* w2g = (const float4*)W2;
        for (int i = tid; i < 4096; i += FUSED_THREADS) {
            int k = i >> 5, c4 = i & 31;
            float4 a = w1g[i];
            float4 b = w2g[i];
            int kq = k >> 2, kr = k & 3;
            #pragma unroll
            for (int j = 0; j < 4; j++) {
                int c = 4 * c4 + j;
                int addr = c * 128 + 4 * (kq ^ ((c >> 2) & 31)) + kr;
                float av = (j == 0) ? a.x : (j == 1) ? a.y : (j == 2) ? a.z : a.w;
                float bv = (j == 0) ? b.x : (j == 1) ? b.y : (j == 2) ? b.z : b.w;
                W1s[addr] = av;
                W2s[addr] = bv;
            }
        }
        if (tid < 128) { b1s[tid] = b1[tid]; b2s[tid] = b2[tid]; }
    }
    __syncthreads();   // only block-wide sync in kernel

    float bb1[4], bb2[4];
    #pragma unroll
    for (int j = 0; j < 4; j++) { bb1[j] = b1s[lane * 4 + j]; bb2[j] = b2s[lane * 4 + j]; }

    for (int t = blockIdx.x; t < ntiles; t += gridDim.x) {
        const int row0 = t * TILE_ROWS;

        // ---- gather: warp fills its private rows_w[0..7] ----
        for (int rr = 0; rr < ROWS_PER_WARP; rr++) {
            const int row = row0 + wid * ROWS_PER_WARP + rr;
            float4 a = make_float4(0.f, 0.f, 0.f, 0.f);
            if (row < n) {
                a = x4[(size_t)row * 32 + lane];
                const int lo = offs[row];
                const int hi = offs[row + 1];
                for (int base = lo; base < hi; base += 32) {
                    int cnt = hi - base; if (cnt > 32) cnt = 32;
                    int idx = (lane < cnt) ? csr[base + lane] : 0;
                    int j = 0;
                    for (; j + 8 <= cnt; j += 8) {
                        int s0 = __shfl_sync(0xffffffffu, idx, j + 0);
                        int s1 = __shfl_sync(0xffffffffu, idx, j + 1);
                        int s2 = __shfl_sync(0xffffffffu, idx, j + 2);
                        int s3 = __shfl_sync(0xffffffffu, idx, j + 3);
                        int s4 = __shfl_sync(0xffffffffu, idx, j + 4);
                        int s5 = __shfl_sync(0xffffffffu, idx, j + 5);
                        int s6 = __shfl_sync(0xffffffffu, idx, j + 6);
                        int s7 = __shfl_sync(0xffffffffu, idx, j + 7);
                        float4 v0 = __ldg(x4 + (size_t)s0 * 32 + lane);
                        float4 v1 = __ldg(x4 + (size_t)s1 * 32 + lane);
                        float4 v2 = __ldg(x4 + (size_t)s2 * 32 + lane);
                        float4 v3 = __ldg(x4 + (size_t)s3 * 32 + lane);
                        float4 v4 = __ldg(x4 + (size_t)s4 * 32 + lane);
                        float4 v5 = __ldg(x4 + (size_t)s5 * 32 + lane);
                        float4 v6 = __ldg(x4 + (size_t)s6 * 32 + lane);
                        float4 v7 = __ldg(x4 + (size_t)s7 * 32 + lane);
                        a.x += v0.x + v1.x + v2.x + v3.x + v4.x + v5.x + v6.x + v7.x;
                        a.y += v0.y + v1.y + v2.y + v3.y + v4.y + v5.y + v6.y + v7.y;
                        a.z += v0.z + v1.z + v2.z + v3.z + v4.z + v5.z + v6.z + v7.z;
                        a.w += v0.w + v1.w + v2.w + v3.w + v4.w + v5.w + v6.w + v7.w;
                    }
                    for (; j < cnt; j++) {
                        int s = __shfl_sync(0xffffffffu, idx, j);
                        float4 v = __ldg(x4 + (size_t)s * 32 + lane);
                        a.x += v.x; a.y += v.y; a.z += v.z; a.w += v.w;
                    }
                }
            }
            *(float4*)(rows_w + rr * 128 + lane * 4) = a;
        }
        __syncwarp();   // rows STS -> GEMM1 LDS

        // ---- GEMM1: h = relu(rows @ W1 + b1), h overwrites rows in place ----
        {
            ull acc[ROWS_PER_WARP][4];
            #pragma unroll
            for (int r = 0; r < ROWS_PER_WARP; r++)
                #pragma unroll
                for (int j = 0; j < 4; j++) acc[r][j] = pack2(bb1[j], 0.f);

            const float* wb = W1s + (lane * 4) * 128;
            #pragma unroll 2
            for (int kq = 0; kq < 32; kq++) {
                const int ch = (kq ^ lane) << 2;
                ulonglong2 w0 = *(const ulonglong2*)(wb + ch);
                ulonglong2 w1 = *(const ulonglong2*)(wb + 128 + ch);
                ulonglong2 w2 = *(const ulonglong2*)(wb + 256 + ch);
                ulonglong2 w3 = *(const ulonglong2*)(wb + 384 + ch);
                #pragma unroll
                for (int r = 0; r < ROWS_PER_WARP; r += 2) {
                    ulonglong2 va = *(const ulonglong2*)(rows_w + r * 128 + kq * 4);
                    ulonglong2 vb = *(const ulonglong2*)(rows_w + (r + 1) * 128 + kq * 4);
                    fma2(acc[r][0], w0.x, va.x); fma2(acc[r][1], w1.x, va.x);
                    fma2(acc[r][2], w2.x, va.x); fma2(acc[r][3], w3.x, va.x);
                    fma2(acc[r+1][0], w0.x, vb.x); fma2(acc[r+1][1], w1.x, vb.x);
                    fma2(acc[r+1][2], w2.x, vb.x); fma2(acc[r+1][3], w3.x, vb.x);
                    fma2(acc[r][0], w0.y, va.y); fma2(acc[r][1], w1.y, va.y);
                    fma2(acc[r][2], w2.y, va.y); fma2(acc[r][3], w3.y, va.y);
                    fma2(acc[r+1][0], w0.y, vb.y); fma2(acc[r+1][1], w1.y, vb.y);
                    fma2(acc[r+1][2], w2.y, vb.y); fma2(acc[r+1][3], w3.y, vb.y);
                }
            }
            __syncwarp();   // all lanes finished READING rows before overwrite
            #pragma unroll
            for (int r = 0; r < ROWS_PER_WARP; r++) {
                float2 p0 = unpack2(acc[r][0]);
                float2 p1 = unpack2(acc[r][1]);
                float2 p2 = unpack2(acc[r][2]);
                float2 p3 = unpack2(acc[r][3]);
                float4 h = make_float4(fmaxf(p0.x + p0.y, 0.f), fmaxf(p1.x + p1.y, 0.f),
                                       fmaxf(p2.x + p2.y, 0.f), fmaxf(p3.x + p3.y, 0.f));
                *(float4*)(rows_w + r * 128 + lane * 4) = h;
            }
        }
        __syncwarp();   // h STS -> GEMM2 LDS

        // ---- GEMM2: xout = h @ W2 + b2 ----
        {
            ull acc[ROWS_PER_WARP][4];
            #pragma unroll
            for (int r = 0; r < ROWS_PER_WARP; r++)
                #pragma unroll
                for (int j = 0; j < 4; j++) acc[r][j] = pack2(bb2[j], 0.f);

            const float* wb = W2s + (lane * 4) * 128;
            #pragma unroll 2
            for (int kq = 0; kq < 32; kq++) {
                const int ch = (kq ^ lane) << 2;
                ulonglong2 w0 = *(const ulonglong2*)(wb + ch);
                ulonglong2 w1 = *(const ulonglong2*)(wb + 128 + ch);
                ulonglong2 w2 = *(const ulonglong2*)(wb + 256 + ch);
                ulonglong2 w3 = *(const ulonglong2*)(wb + 384 + ch);
                #pragma unroll
                for (int r = 0; r < ROWS_PER_WARP; r += 2) {
                    ulonglong2 va = *(const ulonglong2*)(rows_w + r * 128 + kq * 4);
                    ulonglong2 vb = *(const ulonglong2*)(rows_w + (r + 1) * 128 + kq * 4);
                    fma2(acc[r][0], w0.x, va.x); fma2(acc[r][1], w1.x, va.x);
                    fma2(acc[r][2], w2.x, va.x); fma2(acc[r][3], w3.x, va.x);
                    fma2(acc[r+1][0], w0.x, vb.x); fma2(acc[r+1][1], w1.x, vb.x);
                    fma2(acc[r+1][2], w2.x, vb.x); fma2(acc[r+1][3], w3.x, vb.x);
                    fma2(acc[r][0], w0.y, va.y); fma2(acc[r][1], w1.y, va.y);
                    fma2(acc[r][2], w2.y, va.y); fma2(acc[r][3], w3.y, va.y);
                    fma2(acc[r+1][0], w0.y, vb.y); fma2(acc[r+1][1], w1.y, vb.y);
                    fma2(acc[r+1][2], w2.y, vb.y); fma2(acc[r+1][3], w3.y, vb.y);
                }
            }
            #pragma unroll
            for (int r = 0; r < ROWS_PER_WARP; r++) {
                int row = row0 + wid * ROWS_PER_WARP + r;
                if (row < n) {
                    float2 p0 = unpack2(acc[r][0]);
                    float2 p1 = unpack2(acc[r][1]);
                    float2 p2 = unpack2(acc[r][2]);
                    float2 p3 = unpack2(acc[r][3]);
                    *(float4*)(xout + (size_t)row * 128 + lane * 4) =
                        make_float4(p0.x + p0.y, p1.x + p1.y, p2.x + p2.y, p3.x + p3.y);
                }
            }
        }
        __syncwarp();   // GEMM2 reads done before next tile's gather rewrites rows_w
    }
}

// ================= readout =================
__device__ __forceinline__ int lower_bound_i(const int* __restrict__ a, int lo, int hi, int v) {
    while (lo < hi) {
        int m = (lo + hi) >> 1;
        if (a[m] < v) lo = m + 1; else hi = m;
    }
    return lo;
}

__global__ void readout_kernel(float* __restrict__ out, const float* __restrict__ xf,
                               const int* __restrict__ batch, int n) {
    const int g = blockIdx.x;
    const int j = threadIdx.x;
    int lo = lower_bound_i(batch, 0, n, g);
    int hi = lower_bound_i(batch, lo, n, g + 1);
    float s0 = 0.f, s1 = 0.f, s2 = 0.f, s3 = 0.f;
    int r = lo;
    for (; r + 4 <= hi; r += 4) {
        s0 += xf[(size_t)(r + 0) * D + j];
        s1 += xf[(size_t)(r + 1) * D + j];
        s2 += xf[(size_t)(r + 2) * D + j];
        s3 += xf[(size_t)(r + 3) * D + j];
    }
    for (; r < hi; r++) s0 += xf[(size_t)r * D + j];
    out[(size_t)g * D + j] = (s0 + s1) + (s2 + s3);
}

// ================= launch =================
extern "C" void kernel_launch(void* const* d_in, const int* in_sizes, int n_in,
                              void* d_out, int out_size) {
    const float* x   = (const float*)d_in[0];
    const float* W1  = (const float*)d_in[1];
    const float* b1  = (const float*)d_in[2];
    const float* W2  = (const float*)d_in[3];
    const float* b2  = (const float*)d_in[4];
    const int* ei    = (const int*)d_in[5];
    const int* bat   = (const int*)d_in[6];
    float* out       = (float*)d_out;

    const int N = in_sizes[0] / D;
    const int E = in_sizes[5] / 2;
    const int n_layers = in_sizes[1] / (D * D);

    float *xA, *xB;
    int *counts, *offs, *cursor, *csr;
    cudaGetSymbolAddress((void**)&xA, g_xA);
    cudaGetSymbolAddress((void**)&xB, g_xB);
    cudaGetSymbolAddress((void**)&counts, g_counts);
    cudaGetSymbolAddress((void**)&offs, g_offs);
    cudaGetSymbolAddress((void**)&cursor, g_cursor);
    cudaGetSymbolAddress((void**)&csr, g_csr_src);

    const int smem_bytes = (16384 * 3 + 256) * 4;  // 197632
    cudaFuncSetAttribute(fused_layer_kernel, cudaFuncAttributeMaxDynamicSharedMemorySize, smem_bytes);

    // ---- CSR build ----
    cudaMemsetAsync(counts, 0, (size_t)N * sizeof(int), 0);
    hist_kernel<<<(E + 255) / 256, 256>>>(ei, E, counts);      // launch 1
    scan_kernel<<<1, 1024>>>(counts, N, E, offs, cursor);      // launch 2
    fill_kernel<<<(E + 255) / 256, 256>>>(ei, E, cursor, csr); // launch 3

    // ---- layers: launch 4 (profiled), 5, 6 ----
    const int ntiles = (N + TILE_ROWS - 1) / TILE_ROWS;
    const float* xin = x;
    float* bufs[2] = { xA, xB };

    for (int l = 0; l < n_layers; l++) {
        fused_layer_kernel<<<148, FUSED_THREADS, smem_bytes>>>(
            (const float4*)xin,
            W1 + (size_t)l * D * D, b1 + (size_t)l * D,
            W2 + (size_t)l * D * D, b2 + (size_t)l * D,
            offs, csr, bufs[l & 1], N, ntiles);
        xin = bufs[l & 1];
    }

    readout_kernel<<<128, D>>>(out, xin, bat, N);
}

// round 10
// speedup vs baseline: 2.8952x; 1.0181x over previous
#include <cuda_runtime.h>
#include <cuda_bf16.h>
#include <cstdint>

#define D 128
#define TILE_ROWS 96
#define FUSED_THREADS 512
#define ROWS_PER_WARP 6

typedef unsigned long long ull;

// -------- scratch (no cudaMalloc allowed) --------
#define MAX_NODES 100000
#define MAX_EDGES 1600000
__device__ float g_xA[(size_t)MAX_NODES * D];
__device__ float g_xB[(size_t)MAX_NODES * D];
__device__ int   g_counts[MAX_NODES];
__device__ int   g_offs[MAX_NODES + 1];
__device__ int   g_cursor[MAX_NODES];
__device__ int   g_csr_src[MAX_EDGES];

// -------- packed fp32x2 helpers (Blackwell FFMA2) --------
__device__ __forceinline__ ull pack2(float lo, float hi) {
    ull r; asm("mov.b64 %0, {%1,%2};" : "=l"(r) : "f"(lo), "f"(hi)); return r;
}
__device__ __forceinline__ void fma2(ull &d, ull a, ull b) {
    asm("fma.rn.f32x2 %0, %1, %2, %0;" : "+l"(d) : "l"(a), "l"(b));
}
__device__ __forceinline__ float2 unpack2(ull v) {
    float2 f; asm("mov.b64 {%0,%1}, %2;" : "=f"(f.x), "=f"(f.y) : "l"(v)); return f;
}
__device__ __forceinline__ void add4(float4 &a, const float4 &v) {
    a.x += v.x; a.y += v.y; a.z += v.z; a.w += v.w;
}

// ================= CSR build =================
__global__ void hist_kernel(const int* __restrict__ ei, int E, int* __restrict__ counts) {
    int e = blockIdx.x * blockDim.x + threadIdx.x;
    if (e < E) atomicAdd(&counts[ei[(size_t)E + e]], 1);
}

__global__ void scan_kernel(const int* __restrict__ counts, int N, int E,
                            int* __restrict__ offs, int* __restrict__ cursor) {
    __shared__ int sm[1024];
    const int tid = threadIdx.x;
    const int chunk = (N + 1023) / 1024;
    const int lo = tid * chunk;
    const int hi = min(lo + chunk, N);
    int s = 0;
    for (int i = lo; i < hi; i++) s += counts[i];
    sm[tid] = s;
    __syncthreads();
    for (int off = 1; off < 1024; off <<= 1) {
        int t = (tid >= off) ? sm[tid - off] : 0;
        __syncthreads();
        sm[tid] += t;
        __syncthreads();
    }
    int run = sm[tid] - s;
    for (int i = lo; i < hi; i++) {
        int c = counts[i];
        offs[i] = run; cursor[i] = run;
        run += c;
    }
    if (tid == 0) offs[N] = E;
}

__global__ void fill_kernel(const int* __restrict__ ei, int E,
                            int* __restrict__ cursor, int* __restrict__ csr_src) {
    int e = blockIdx.x * blockDim.x + threadIdx.x;
    if (e < E) {
        int d = ei[(size_t)E + e];
        int pos = atomicAdd(&cursor[d], 1);
        csr_src[pos] = ei[e];
    }
}

// ================= fused layer (R7 GEMM + half-warp-paired gather) =================
// GEMM identical to R7 (best measured): W^T XOR-swizzled, 6 rows/warp, separate hs,
// warp-autonomous tile loop (no __syncthreads after W staging).
// Gather: one row per HALF-WARP (lane>>4 selects row of the pair). Doubles the
// per-warp memory-level parallelism and halves the serial idx->load chains.
// Cross-half divergence removed by maxing loop bounds across halves
// (__shfl_xor_sync width-16 exchange) + predicated accumulation, so every
// full-mask __shfl_sync is executed by all 32 lanes.
__global__ void __launch_bounds__(FUSED_THREADS, 1) fused_layer_kernel(
    const float4* __restrict__ x4,
    const float* __restrict__ W1, const float* __restrict__ b1,
    const float* __restrict__ W2, const float* __restrict__ b2,
    const int* __restrict__ offs, const int* __restrict__ csr,
    float* __restrict__ xout, int n, int ntiles)
{
    extern __shared__ float smem[];
    float* W1s  = smem;                 // 16384 floats (transposed + swizzled)
    float* W2s  = W1s + 16384;          // 16384
    float* rows = W2s + 16384;          // 96*128 = 12288
    float* hs   = rows + 12288;         // 12288

    const int tid  = threadIdx.x;
    const int lane = tid & 31;
    const int wid  = tid >> 5;          // warp 0..15, owns rows wid*6..wid*6+5
    const int hw   = lane >> 4;         // half-warp id (0/1) -> row of pair
    const int hl   = lane & 15;         // lane within half

    // ---- stage W1^T, W2^T with XOR swizzle ----
    {
        const float4* w1g = (const float4*)W1;
        const float4* w2g = (const float4*)W2;
        for (int i = tid; i < 4096; i += FUSED_THREADS) {
            int k = i >> 5, c4 = i & 31;
            float4 a = w1g[i];
            float4 b = w2g[i];
            int kq = k >> 2, kr = k & 3;
            #pragma unroll
            for (int j = 0; j < 4; j++) {
                int c = 4 * c4 + j;
                int addr = c * 128 + 4 * (kq ^ ((c >> 2) & 31)) + kr;
                float av = (j == 0) ? a.x : (j == 1) ? a.y : (j == 2) ? a.z : a.w;
                float bv = (j == 0) ? b.x : (j == 1) ? b.y : (j == 2) ? b.z : b.w;
                W1s[addr] = av;
                W2s[addr] = bv;
            }
        }
    }
    float bb1[4], bb2[4];
    #pragma unroll
    for (int j = 0; j < 4; j++) { bb1[j] = b1[lane * 4 + j]; bb2[j] = b2[lane * 4 + j]; }
    __syncthreads();   // W visible; only block-wide sync in kernel

    for (int t = blockIdx.x; t < ntiles; t += gridDim.x) {
        const int row0 = t * TILE_ROWS;

        // ---- gather: 3 row-pairs, one row per half-warp ----
        for (int rr = 0; rr < ROWS_PER_WARP; rr += 2) {
            const int lr  = wid * ROWS_PER_WARP + rr + hw;
            const int row = row0 + lr;
            float4 a0 = make_float4(0.f, 0.f, 0.f, 0.f);
            float4 a1 = make_float4(0.f, 0.f, 0.f, 0.f);
            int lo = 0, deg = 0;
            if (row < n) {
                lo  = offs[row];
                deg = offs[row + 1] - lo;
                a0 = x4[(size_t)row * 32 + hl * 2];
                a1 = x4[(size_t)row * 32 + hl * 2 + 1];
            }
            int nb = (deg + 15) >> 4;
            int nbo = __shfl_xor_sync(0xffffffffu, nb, 16);
            int nbmax = nb > nbo ? nb : nbo;
            for (int b = 0; b < nbmax; b++) {
                int rem = deg - b * 16;
                int cnt = rem < 0 ? 0 : (rem > 16 ? 16 : rem);
                int idx = (hl < cnt) ? __ldg(csr + lo + b * 16 + hl) : 0;
                int cnto = __shfl_xor_sync(0xffffffffu, cnt, 16);
                int cmax = cnt > cnto ? cnt : cnto;
                int j = 0;
                for (; j + 4 <= cmax; j += 4) {
                    int s0 = __shfl_sync(0xffffffffu, idx, j + 0, 16);
                    int s1 = __shfl_sync(0xffffffffu, idx, j + 1, 16);
                    int s2 = __shfl_sync(0xffffffffu, idx, j + 2, 16);
                    int s3 = __shfl_sync(0xffffffffu, idx, j + 3, 16);
                    float4 u0a = __ldg(x4 + (size_t)s0 * 32 + hl * 2);
                    float4 u0b = __ldg(x4 + (size_t)s0 * 32 + hl * 2 + 1);
                    float4 u1a = __ldg(x4 + (size_t)s1 * 32 + hl * 2);
                    float4 u1b = __ldg(x4 + (size_t)s1 * 32 + hl * 2 + 1);
                    float4 u2a = __ldg(x4 + (size_t)s2 * 32 + hl * 2);
                    float4 u2b = __ldg(x4 + (size_t)s2 * 32 + hl * 2 + 1);
                    float4 u3a = __ldg(x4 + (size_t)s3 * 32 + hl * 2);
                    float4 u3b = __ldg(x4 + (size_t)s3 * 32 + hl * 2 + 1);
                    if (j + 0 < cnt) { add4(a0, u0a); add4(a1, u0b); }
                    if (j + 1 < cnt) { add4(a0, u1a); add4(a1, u1b); }
                    if (j + 2 < cnt) { add4(a0, u2a); add4(a1, u2b); }
                    if (j + 3 < cnt) { add4(a0, u3a); add4(a1, u3b); }
                }
                for (; j < cmax; j++) {
                    int s = __shfl_sync(0xffffffffu, idx, j, 16);
                    float4 ua = __ldg(x4 + (size_t)s * 32 + hl * 2);
                    float4 ub = __ldg(x4 + (size_t)s * 32 + hl * 2 + 1);
                    if (j < cnt) { add4(a0, ua); add4(a1, ub); }
                }
            }
            *(float4*)(rows + lr * 128 + hl * 8)     = a0;
            *(float4*)(rows + lr * 128 + hl * 8 + 4) = a1;
        }
        __syncwarp();   // rows STS -> GEMM1 LDS (warp-local)

        // ---- GEMM1: hs = relu(rows @ W1 + b1) ----
        {
            ull acc[ROWS_PER_WARP][4];
            #pragma unroll
            for (int r = 0; r < ROWS_PER_WARP; r++)
                #pragma unroll
                for (int j = 0; j < 4; j++) acc[r][j] = pack2(bb1[j], 0.f);

            const float* wb = W1s + (lane * 4) * 128;
            const float* rb = rows + (wid * ROWS_PER_WARP) * 128;
            #pragma unroll 2
            for (int kq = 0; kq < 32; kq++) {
                const int ch = (kq ^ lane) << 2;
                ulonglong2 w0 = *(const ulonglong2*)(wb + ch);
                ulonglong2 w1 = *(const ulonglong2*)(wb + 128 + ch);
                ulonglong2 w2 = *(const ulonglong2*)(wb + 256 + ch);
                ulonglong2 w3 = *(const ulonglong2*)(wb + 384 + ch);
                #pragma unroll
                for (int r = 0; r < ROWS_PER_WARP; r += 2) {
                    ulonglong2 va = *(const ulonglong2*)(rb + r * 128 + kq * 4);
                    ulonglong2 vb = *(const ulonglong2*)(rb + (r + 1) * 128 + kq * 4);
                    fma2(acc[r][0], w0.x, va.x); fma2(acc[r][1], w1.x, va.x);
                    fma2(acc[r][2], w2.x, va.x); fma2(acc[r][3], w3.x, va.x);
                    fma2(acc[r+1][0], w0.x, vb.x); fma2(acc[r+1][1], w1.x, vb.x);
                    fma2(acc[r+1][2], w2.x, vb.x); fma2(acc[r+1][3], w3.x, vb.x);
                    fma2(acc[r][0], w0.y, va.y); fma2(acc[r][1], w1.y, va.y);
                    fma2(acc[r][2], w2.y, va.y); fma2(acc[r][3], w3.y, va.y);
                    fma2(acc[r+1][0], w0.y, vb.y); fma2(acc[r+1][1], w1.y, vb.y);
                    fma2(acc[r+1][2], w2.y, vb.y); fma2(acc[r+1][3], w3.y, vb.y);
                }
            }
            #pragma unroll
            for (int r = 0; r < ROWS_PER_WARP; r++) {
                float2 p0 = unpack2(acc[r][0]);
                float2 p1 = unpack2(acc[r][1]);
                float2 p2 = unpack2(acc[r][2]);
                float2 p3 = unpack2(acc[r][3]);
                float4 h = make_float4(fmaxf(p0.x + p0.y, 0.f), fmaxf(p1.x + p1.y, 0.f),
                                       fmaxf(p2.x + p2.y, 0.f), fmaxf(p3.x + p3.y, 0.f));
                *(float4*)(hs + (wid * ROWS_PER_WARP + r) * 128 + lane * 4) = h;
            }
        }
        __syncwarp();   // hs STS -> GEMM2 LDS; also fences rows reads before next gather

        // ---- GEMM2: xout = hs @ W2 + b2 ----
        {
            ull acc[ROWS_PER_WARP][4];
            #pragma unroll
            for (int r = 0; r < ROWS_PER_WARP; r++)
                #pragma unroll
                for (int j = 0; j < 4; j++) acc[r][j] = pack2(bb2[j], 0.f);

            const float* wb = W2s + (lane * 4) * 128;
            const float* rb = hs + (wid * ROWS_PER_WARP) * 128;
            #pragma unroll 2
            for (int kq = 0; kq < 32; kq++) {
                const int ch = (kq ^ lane) << 2;
                ulonglong2 w0 = *(const ulonglong2*)(wb + ch);
                ulonglong2 w1 = *(const ulonglong2*)(wb + 128 + ch);
                ulonglong2 w2 = *(const ulonglong2*)(wb + 256 + ch);
                ulonglong2 w3 = *(const ulonglong2*)(wb + 384 + ch);
                #pragma unroll
                for (int r = 0; r < ROWS_PER_WARP; r += 2) {
                    ulonglong2 va = *(const ulonglong2*)(rb + r * 128 + kq * 4);
                    ulonglong2 vb = *(const ulonglong2*)(rb + (r + 1) * 128 + kq * 4);
                    fma2(acc[r][0], w0.x, va.x); fma2(acc[r][1], w1.x, va.x);
                    fma2(acc[r][2], w2.x, va.x); fma2(acc[r][3], w3.x, va.x);
                    fma2(acc[r+1][0], w0.x, vb.x); fma2(acc[r+1][1], w1.x, vb.x);
                    fma2(acc[r+1][2], w2.x, vb.x); fma2(acc[r+1][3], w3.x, vb.x);
                    fma2(acc[r][0], w0.y, va.y); fma2(acc[r][1], w1.y, va.y);
                    fma2(acc[r][2], w2.y, va.y); fma2(acc[r][3], w3.y, va.y);
                    fma2(acc[r+1][0], w0.y, vb.y); fma2(acc[r+1][1], w1.y, vb.y);
                    fma2(acc[r+1][2], w2.y, vb.y); fma2(acc[r+1][3], w3.y, vb.y);
                }
            }
            #pragma unroll
            for (int r = 0; r < ROWS_PER_WARP; r++) {
                int row = row0 + wid * ROWS_PER_WARP + r;
                if (row < n) {
                    float2 p0 = unpack2(acc[r][0]);
                    float2 p1 = unpack2(acc[r][1]);
                    float2 p2 = unpack2(acc[r][2]);
                    float2 p3 = unpack2(acc[r][3]);
                    *(float4*)(xout + (size_t)row * 128 + lane * 4) =
                        make_float4(p0.x + p0.y, p1.x + p1.y, p2.x + p2.y, p3.x + p3.y);
                }
            }
        }
        __syncwarp();   // hs reads done before next tile's GEMM1 rewrites hs
    }
}

// ================= readout =================
__device__ __forceinline__ int lower_bound_i(const int* __restrict__ a, int lo, int hi, int v) {
    while (lo < hi) {
        int m = (lo + hi) >> 1;
        if (a[m] < v) lo = m + 1; else hi = m;
    }
    return lo;
}

__global__ void readout_kernel(float* __restrict__ out, const float* __restrict__ xf,
                               const int* __restrict__ batch, int n) {
    const int g = blockIdx.x;
    const int j = threadIdx.x;
    int lo = lower_bound_i(batch, 0, n, g);
    int hi = lower_bound_i(batch, lo, n, g + 1);
    float s0 = 0.f, s1 = 0.f, s2 = 0.f, s3 = 0.f;
    int r = lo;
    for (; r + 4 <= hi; r += 4) {
        s0 += xf[(size_t)(r + 0) * D + j];
        s1 += xf[(size_t)(r + 1) * D + j];
        s2 += xf[(size_t)(r + 2) * D + j];
        s3 += xf[(size_t)(r + 3) * D + j];
    }
    for (; r < hi; r++) s0 += xf[(size_t)r * D + j];
    out[(size_t)g * D + j] = (s0 + s1) + (s2 + s3);
}

// ================= launch =================
extern "C" void kernel_launch(void* const* d_in, const int* in_sizes, int n_in,
                              void* d_out, int out_size) {
    const float* x   = (const float*)d_in[0];
    const float* W1  = (const float*)d_in[1];
    const float* b1  = (const float*)d_in[2];
    const float* W2  = (const float*)d_in[3];
    const float* b2  = (const float*)d_in[4];
    const int* ei    = (const int*)d_in[5];
    const int* bat   = (const int*)d_in[6];
    float* out       = (float*)d_out;

    const int N = in_sizes[0] / D;
    const int E = in_sizes[5] / 2;
    const int n_layers = in_sizes[1] / (D * D);

    float *xA, *xB;
    int *counts, *offs, *cursor, *csr;
    cudaGetSymbolAddress((void**)&xA, g_xA);
    cudaGetSymbolAddress((void**)&xB, g_xB);
    cudaGetSymbolAddress((void**)&counts, g_counts);
    cudaGetSymbolAddress((void**)&offs, g_offs);
    cudaGetSymbolAddress((void**)&cursor, g_cursor);
    cudaGetSymbolAddress((void**)&csr, g_csr_src);

    const int smem_bytes = (16384 * 2 + 12288 * 2) * 4;  // 229376
    cudaFuncSetAttribute(fused_layer_kernel, cudaFuncAttributeMaxDynamicSharedMemorySize, smem_bytes);

    // ---- CSR build ----
    cudaMemsetAsync(counts, 0, (size_t)N * sizeof(int), 0);
    hist_kernel<<<(E + 255) / 256, 256>>>(ei, E, counts);      // launch 1
    scan_kernel<<<1, 1024>>>(counts, N, E, offs, cursor);      // launch 2
    fill_kernel<<<(E + 255) / 256, 256>>>(ei, E, cursor, csr); // launch 3

    // ---- layers: launch 4 (profiled), 5, 6 ----
    const int ntiles = (N + TILE_ROWS - 1) / TILE_ROWS;
    const float* xin = x;
    float* bufs[2] = { xA, xB };

    for (int l = 0; l < n_layers; l++) {
        fused_layer_kernel<<<148, FUSED_THREADS, smem_bytes>>>(
            (const float4*)xin,
            W1 + (size_t)l * D * D, b1 + (size_t)l * D,
            W2 + (size_t)l * D * D, b2 + (size_t)l * D,
            offs, csr, bufs[l & 1], N, ntiles);
        xin = bufs[l & 1];
    }

    readout_kernel<<<128, D>>>(out, xin, bat, N);
}

// round 11
// speedup vs baseline: 2.8953x; 1.0001x over previous
#include <cuda_runtime.h>
#include <cuda_bf16.h>
#include <cstdint>

#define D 128
#define TILE_ROWS 96
#define MLP_THREADS 512
#define ROWS_PER_WARP 6

typedef unsigned long long ull;

// -------- scratch (no cudaMalloc allowed) --------
#define MAX_NODES 100000
#define MAX_EDGES 1600000
__device__ float g_acc[(size_t)MAX_NODES * D];
__device__ float g_xA[(size_t)MAX_NODES * D];
__device__ float g_xB[(size_t)MAX_NODES * D];
__device__ int   g_counts[MAX_NODES];
__device__ int   g_offs[MAX_NODES + 1];
__device__ int   g_cursor[MAX_NODES];
__device__ int   g_csr_src[MAX_EDGES];

// -------- packed fp32x2 helpers (Blackwell FFMA2) --------
__device__ __forceinline__ ull pack2(float lo, float hi) {
    ull r; asm("mov.b64 %0, {%1,%2};" : "=l"(r) : "f"(lo), "f"(hi)); return r;
}
__device__ __forceinline__ void fma2(ull &d, ull a, ull b) {
    asm("fma.rn.f32x2 %0, %1, %2, %0;" : "+l"(d) : "l"(a), "l"(b));
}
__device__ __forceinline__ float2 unpack2(ull v) {
    float2 f; asm("mov.b64 {%0,%1}, %2;" : "=f"(f.x), "=f"(f.y) : "l"(v)); return f;
}

// ================= CSR build =================
__global__ void hist_kernel(const int* __restrict__ ei, int E, int* __restrict__ counts) {
    int e = blockIdx.x * blockDim.x + threadIdx.x;
    if (e < E) atomicAdd(&counts[ei[(size_t)E + e]], 1);
}

__global__ void scan_kernel(const int* __restrict__ counts, int N, int E,
                            int* __restrict__ offs, int* __restrict__ cursor) {
    __shared__ int sm[1024];
    const int tid = threadIdx.x;
    const int chunk = (N + 1023) / 1024;
    const int lo = tid * chunk;
    const int hi = min(lo + chunk, N);
    int s = 0;
    for (int i = lo; i < hi; i++) s += counts[i];
    sm[tid] = s;
    __syncthreads();
    for (int off = 1; off < 1024; off <<= 1) {
        int t = (tid >= off) ? sm[tid - off] : 0;
        __syncthreads();
        sm[tid] += t;
        __syncthreads();
    }
    int run = sm[tid] - s;
    for (int i = lo; i < hi; i++) {
        int c = counts[i];
        offs[i] = run; cursor[i] = run;
        run += c;
    }
    if (tid == 0) offs[N] = E;
}

__global__ void fill_kernel(const int* __restrict__ ei, int E,
                            int* __restrict__ cursor, int* __restrict__ csr_src) {
    int e = blockIdx.x * blockDim.x + threadIdx.x;
    if (e < E) {
        int d = ei[(size_t)E + e];
        int pos = atomicAdd(&cursor[d], 1);
        csr_src[pos] = ei[e];
    }
}

// ================= standalone gather: acc[v] = x[v] + sum_{u in in(v)} x[u] =================
// Warp per node, no SMEM, low regs -> high occupancy (32-48 warps/SM) so the
// 250-cycle L2 latency chains of many nodes overlap. This is the fix for the
// fused kernel's 24%-occupancy latency starvation.
__global__ void gather_kernel(float4* __restrict__ acc, const float4* __restrict__ x,
                              const int* __restrict__ offs, const int* __restrict__ csr,
                              int N) {
    int warp = (blockIdx.x * blockDim.x + threadIdx.x) >> 5;
    int lane = threadIdx.x & 31;
    if (warp >= N) return;
    int lo = offs[warp];
    int hi = offs[warp + 1];
    float4 a = x[(size_t)warp * 32 + lane];
    for (int base = lo; base < hi; base += 32) {
        int cnt = hi - base; if (cnt > 32) cnt = 32;
        int idx = (lane < cnt) ? __ldg(csr + base + lane) : 0;
        int j = 0;
        for (; j + 8 <= cnt; j += 8) {
            int s0 = __shfl_sync(0xffffffffu, idx, j + 0);
            int s1 = __shfl_sync(0xffffffffu, idx, j + 1);
            int s2 = __shfl_sync(0xffffffffu, idx, j + 2);
            int s3 = __shfl_sync(0xffffffffu, idx, j + 3);
            int s4 = __shfl_sync(0xffffffffu, idx, j + 4);
            int s5 = __shfl_sync(0xffffffffu, idx, j + 5);
            int s6 = __shfl_sync(0xffffffffu, idx, j + 6);
            int s7 = __shfl_sync(0xffffffffu, idx, j + 7);
            float4 v0 = __ldg(x + (size_t)s0 * 32 + lane);
            float4 v1 = __ldg(x + (size_t)s1 * 32 + lane);
            float4 v2 = __ldg(x + (size_t)s2 * 32 + lane);
            float4 v3 = __ldg(x + (size_t)s3 * 32 + lane);
            float4 v4 = __ldg(x + (size_t)s4 * 32 + lane);
            float4 v5 = __ldg(x + (size_t)s5 * 32 + lane);
            float4 v6 = __ldg(x + (size_t)s6 * 32 + lane);
            float4 v7 = __ldg(x + (size_t)s7 * 32 + lane);
            a.x += v0.x + v1.x + v2.x + v3.x + v4.x + v5.x + v6.x + v7.x;
            a.y += v0.y + v1.y + v2.y + v3.y + v4.y + v5.y + v6.y + v7.y;
            a.z += v0.z + v1.z + v2.z + v3.z + v4.z + v5.z + v6.z + v7.z;
            a.w += v0.w + v1.w + v2.w + v3.w + v4.w + v5.w + v6.w + v7.w;
        }
        for (; j < cnt; j++) {
            int s = __shfl_sync(0xffffffffu, idx, j);
            float4 v = __ldg(x + (size_t)s * 32 + lane);
            a.x += v.x; a.y += v.y; a.z += v.z; a.w += v.w;
        }
    }
    acc[(size_t)warp * 32 + lane] = a;
}

// ================= standalone MLP: xout = relu(acc@W1+b1)@W2+b2 =================
// R7 GEMM core (proven conflict-free XOR swizzle, warp-autonomous, 6 rows/warp).
// Row staging is now 6 INDEPENDENT coalesced LDG.128 per warp from acc -> one
// latency wait per tile instead of a serial per-edge chain; GEMM dominates wall.
__global__ void __launch_bounds__(MLP_THREADS, 1) mlp_kernel(
    const float4* __restrict__ acc4,
    const float* __restrict__ W1, const float* __restrict__ b1,
    const float* __restrict__ W2, const float* __restrict__ b2,
    float* __restrict__ xout, int n, int ntiles)
{
    extern __shared__ float smem[];
    float* W1s  = smem;                 // 16384 floats (transposed + swizzled)
    float* W2s  = W1s + 16384;          // 16384
    float* rows = W2s + 16384;          // 96*128 = 12288
    float* hs   = rows + 12288;         // 12288

    const int tid  = threadIdx.x;
    const int lane = tid & 31;
    const int wid  = tid >> 5;          // warp 0..15, owns rows wid*6..wid*6+5

    // ---- stage W1^T, W2^T with XOR swizzle:
    //      element (c,k) at word c*128 + 4*((k>>2) ^ ((c>>2)&31)) + (k&3) ----
    {
        const float4* w1g = (const float4*)W1;
        const float4* w2g = (const float4*)W2;
        for (int i = tid; i < 4096; i += MLP_THREADS) {
            int k = i >> 5, c4 = i & 31;
            float4 a = w1g[i];
            float4 b = w2g[i];
            int kq = k >> 2, kr = k & 3;
            #pragma unroll
            for (int j = 0; j < 4; j++) {
                int c = 4 * c4 + j;
                int addr = c * 128 + 4 * (kq ^ ((c >> 2) & 31)) + kr;
                float av = (j == 0) ? a.x : (j == 1) ? a.y : (j == 2) ? a.z : a.w;
                float bv = (j == 0) ? b.x : (j == 1) ? b.y : (j == 2) ? b.z : b.w;
                W1s[addr] = av;
                W2s[addr] = bv;
            }
        }
    }
    float bb1[4], bb2[4];
    #pragma unroll
    for (int j = 0; j < 4; j++) { bb1[j] = b1[lane * 4 + j]; bb2[j] = b2[lane * 4 + j]; }
    __syncthreads();   // W visible; only block-wide sync in kernel

    for (int t = blockIdx.x; t < ntiles; t += gridDim.x) {
        const int row0 = t * TILE_ROWS;
        const int rbase = row0 + wid * ROWS_PER_WARP;

        // ---- stage 6 rows: independent coalesced loads, one wait ----
        {
            float4 v0 = (rbase + 0 < n) ? __ldg(acc4 + (size_t)(rbase + 0) * 32 + lane) : make_float4(0.f,0.f,0.f,0.f);
            float4 v1 = (rbase + 1 < n) ? __ldg(acc4 + (size_t)(rbase + 1) * 32 + lane) : make_float4(0.f,0.f,0.f,0.f);
            float4 v2 = (rbase + 2 < n) ? __ldg(acc4 + (size_t)(rbase + 2) * 32 + lane) : make_float4(0.f,0.f,0.f,0.f);
            float4 v3 = (rbase + 3 < n) ? __ldg(acc4 + (size_t)(rbase + 3) * 32 + lane) : make_float4(0.f,0.f,0.f,0.f);
            float4 v4 = (rbase + 4 < n) ? __ldg(acc4 + (size_t)(rbase + 4) * 32 + lane) : make_float4(0.f,0.f,0.f,0.f);
            float4 v5 = (rbase + 5 < n) ? __ldg(acc4 + (size_t)(rbase + 5) * 32 + lane) : make_float4(0.f,0.f,0.f,0.f);
            float4* rw = (float4*)(rows + (wid * ROWS_PER_WARP) * 128);
            rw[0 * 32 + lane] = v0;
            rw[1 * 32 + lane] = v1;
            rw[2 * 32 + lane] = v2;
            rw[3 * 32 + lane] = v3;
            rw[4 * 32 + lane] = v4;
            rw[5 * 32 + lane] = v5;
        }
        __syncwarp();

        // ---- GEMM1: hs = relu(rows @ W1 + b1) ----
        {
            ull acc[ROWS_PER_WARP][4];
            #pragma unroll
            for (int r = 0; r < ROWS_PER_WARP; r++)
                #pragma unroll
                for (int j = 0; j < 4; j++) acc[r][j] = pack2(bb1[j], 0.f);

            const float* wb = W1s + (lane * 4) * 128;
            const float* rb = rows + (wid * ROWS_PER_WARP) * 128;
            #pragma unroll 2
            for (int kq = 0; kq < 32; kq++) {
                const int ch = (kq ^ lane) << 2;
                ulonglong2 w0 = *(const ulonglong2*)(wb + ch);
                ulonglong2 w1 = *(const ulonglong2*)(wb + 128 + ch);
                ulonglong2 w2 = *(const ulonglong2*)(wb + 256 + ch);
                ulonglong2 w3 = *(const ulonglong2*)(wb + 384 + ch);
                #pragma unroll
                for (int r = 0; r < ROWS_PER_WARP; r += 2) {
                    ulonglong2 va = *(const ulonglong2*)(rb + r * 128 + kq * 4);
                    ulonglong2 vb = *(const ulonglong2*)(rb + (r + 1) * 128 + kq * 4);
                    fma2(acc[r][0], w0.x, va.x); fma2(acc[r][1], w1.x, va.x);
                    fma2(acc[r][2], w2.x, va.x); fma2(acc[r][3], w3.x, va.x);
                    fma2(acc[r+1][0], w0.x, vb.x); fma2(acc[r+1][1], w1.x, vb.x);
                    fma2(acc[r+1][2], w2.x, vb.x); fma2(acc[r+1][3], w3.x, vb.x);
                    fma2(acc[r][0], w0.y, va.y); fma2(acc[r][1], w1.y, va.y);
                    fma2(acc[r][2], w2.y, va.y); fma2(acc[r][3], w3.y, va.y);
                    fma2(acc[r+1][0], w0.y, vb.y); fma2(acc[r+1][1], w1.y, vb.y);
                    fma2(acc[r+1][2], w2.y, vb.y); fma2(acc[r+1][3], w3.y, vb.y);
                }
            }
            #pragma unroll
            for (int r = 0; r < ROWS_PER_WARP; r++) {
                float2 p0 = unpack2(acc[r][0]);
                float2 p1 = unpack2(acc[r][1]);
                float2 p2 = unpack2(acc[r][2]);
                float2 p3 = unpack2(acc[r][3]);
                float4 h = make_float4(fmaxf(p0.x + p0.y, 0.f), fmaxf(p1.x + p1.y, 0.f),
                                       fmaxf(p2.x + p2.y, 0.f), fmaxf(p3.x + p3.y, 0.f));
                *(float4*)(hs + (wid * ROWS_PER_WARP + r) * 128 + lane * 4) = h;
            }
        }
        __syncwarp();

        // ---- GEMM2: xout = hs @ W2 + b2 ----
        {
            ull acc[ROWS_PER_WARP][4];
            #pragma unroll
            for (int r = 0; r < ROWS_PER_WARP; r++)
                #pragma unroll
                for (int j = 0; j < 4; j++) acc[r][j] = pack2(bb2[j], 0.f);

            const float* wb = W2s + (lane * 4) * 128;
            const float* rb = hs + (wid * ROWS_PER_WARP) * 128;
            #pragma unroll 2
            for (int kq = 0; kq < 32; kq++) {
                const int ch = (kq ^ lane) << 2;
                ulonglong2 w0 = *(const ulonglong2*)(wb + ch);
                ulonglong2 w1 = *(const ulonglong2*)(wb + 128 + ch);
                ulonglong2 w2 = *(const ulonglong2*)(wb + 256 + ch);
                ulonglong2 w3 = *(const ulonglong2*)(wb + 384 + ch);
                #pragma unroll
                for (int r = 0; r < ROWS_PER_WARP; r += 2) {
                    ulonglong2 va = *(const ulonglong2*)(rb + r * 128 + kq * 4);
                    ulonglong2 vb = *(const ulonglong2*)(rb + (r + 1) * 128 + kq * 4);
                    fma2(acc[r][0], w0.x, va.x); fma2(acc[r][1], w1.x, va.x);
                    fma2(acc[r][2], w2.x, va.x); fma2(acc[r][3], w3.x, va.x);
                    fma2(acc[r+1][0], w0.x, vb.x); fma2(acc[r+1][1], w1.x, vb.x);
                    fma2(acc[r+1][2], w2.x, vb.x); fma2(acc[r+1][3], w3.x, vb.x);
                    fma2(acc[r][0], w0.y, va.y); fma2(acc[r][1], w1.y, va.y);
                    fma2(acc[r][2], w2.y, va.y); fma2(acc[r][3], w3.y, va.y);
                    fma2(acc[r+1][0], w0.y, vb.y); fma2(acc[r+1][1], w1.y, vb.y);
                    fma2(acc[r+1][2], w2.y, vb.y); fma2(acc[r+1][3], w3.y, vb.y);
                }
            }
            #pragma unroll
            for (int r = 0; r < ROWS_PER_WARP; r++) {
                int row = rbase + r;
                if (row < n) {
                    float2 p0 = unpack2(acc[r][0]);
                    float2 p1 = unpack2(acc[r][1]);
                    float2 p2 = unpack2(acc[r][2]);
                    float2 p3 = unpack2(acc[r][3]);
                    *(float4*)(xout + (size_t)row * 128 + lane * 4) =
                        make_float4(p0.x + p0.y, p1.x + p1.y, p2.x + p2.y, p3.x + p3.y);
                }
            }
        }
        __syncwarp();   // hs/rows reads done before next tile rewrites
    }
}

// ================= readout =================
__device__ __forceinline__ int lower_bound_i(const int* __restrict__ a, int lo, int hi, int v) {
    while (lo < hi) {
        int m = (lo + hi) >> 1;
        if (a[m] < v) lo = m + 1; else hi = m;
    }
    return lo;
}

__global__ void readout_kernel(float* __restrict__ out, const float* __restrict__ xf,
                               const int* __restrict__ batch, int n) {
    const int g = blockIdx.x;
    const int j = threadIdx.x;
    int lo = lower_bound_i(batch, 0, n, g);
    int hi = lower_bound_i(batch, lo, n, g + 1);
    float s0 = 0.f, s1 = 0.f, s2 = 0.f, s3 = 0.f;
    int r = lo;
    for (; r + 4 <= hi; r += 4) {
        s0 += xf[(size_t)(r + 0) * D + j];
        s1 += xf[(size_t)(r + 1) * D + j];
        s2 += xf[(size_t)(r + 2) * D + j];
        s3 += xf[(size_t)(r + 3) * D + j];
    }
    for (; r < hi; r++) s0 += xf[(size_t)r * D + j];
    out[(size_t)g * D + j] = (s0 + s1) + (s2 + s3);
}

// ================= launch =================
extern "C" void kernel_launch(void* const* d_in, const int* in_sizes, int n_in,
                              void* d_out, int out_size) {
    const float* x   = (const float*)d_in[0];
    const float* W1  = (const float*)d_in[1];
    const float* b1  = (const float*)d_in[2];
    const float* W2  = (const float*)d_in[3];
    const float* b2  = (const float*)d_in[4];
    const int* ei    = (const int*)d_in[5];
    const int* bat   = (const int*)d_in[6];
    float* out       = (float*)d_out;

    const int N = in_sizes[0] / D;
    const int E = in_sizes[5] / 2;
    const int n_layers = in_sizes[1] / (D * D);

    float *acc, *xA, *xB;
    int *counts, *offs, *cursor, *csr;
    cudaGetSymbolAddress((void**)&acc, g_acc);
    cudaGetSymbolAddress((void**)&xA, g_xA);
    cudaGetSymbolAddress((void**)&xB, g_xB);
    cudaGetSymbolAddress((void**)&counts, g_counts);
    cudaGetSymbolAddress((void**)&offs, g_offs);
    cudaGetSymbolAddress((void**)&cursor, g_cursor);
    cudaGetSymbolAddress((void**)&csr, g_csr_src);

    const int smem_bytes = (16384 * 2 + 12288 * 2) * 4;  // 229376
    cudaFuncSetAttribute(mlp_kernel, cudaFuncAttributeMaxDynamicSharedMemorySize, smem_bytes);

    // ---- CSR build ----
    cudaMemsetAsync(counts, 0, (size_t)N * sizeof(int), 0);
    hist_kernel<<<(E + 255) / 256, 256>>>(ei, E, counts);      // launch 1
    scan_kernel<<<1, 1024>>>(counts, N, E, offs, cursor);      // launch 2
    fill_kernel<<<(E + 255) / 256, 256>>>(ei, E, cursor, csr); // launch 3

    // ---- layers: gather (launch 4 = profiled) + MLP per layer ----
    const int ntiles = (N + TILE_ROWS - 1) / TILE_ROWS;
    const int gather_blocks = (N * 32 + 511) / 512;
    const float* xin = x;
    float* bufs[2] = { xA, xB };

    for (int l = 0; l < n_layers; l++) {
        gather_kernel<<<gather_blocks, 512>>>((float4*)acc, (const float4*)xin,
                                              offs, csr, N);
        mlp_kernel<<<148, MLP_THREADS, smem_bytes>>>(
            (const float4*)acc,
            W1 + (size_t)l * D * D, b1 + (size_t)l * D,
            W2 + (size_t)l * D * D, b2 + (size_t)l * D,
            bufs[l & 1], N, ntiles);
        xin = bufs[l & 1];
    }

    readout_kernel<<<128, D>>>(out, xin, bat, N);
}

// round 12
// speedup vs baseline: 3.1163x; 1.0763x over previous
#include <cuda_runtime.h>
#include <cuda_bf16.h>
#include <cstdint>

#define D 128
#define MLP_THREADS 512
#define ROWS_PER_WARP 8

typedef unsigned long long ull;

// -------- scratch (no cudaMalloc allowed) --------
#define MAX_NODES 100000
#define MAX_EDGES 1600000
#define N_GRAPHS_MAX 128
__device__ float g_acc[(size_t)MAX_NODES * D];
__device__ float g_xA[(size_t)MAX_NODES * D];
__device__ float g_xB[(size_t)MAX_NODES * D];
__device__ int   g_counts[MAX_NODES];
__device__ int   g_offs[MAX_NODES + 1];
__device__ int   g_cursor[MAX_NODES];
__device__ int   g_csr_src[MAX_EDGES];
__device__ float g_pool[N_GRAPHS_MAX * D];
__device__ int   g_cnt[N_GRAPHS_MAX];

// -------- packed fp32x2 helpers (Blackwell FFMA2) --------
__device__ __forceinline__ ull pack2(float lo, float hi) {
    ull r; asm("mov.b64 %0, {%1,%2};" : "=l"(r) : "f"(lo), "f"(hi)); return r;
}
__device__ __forceinline__ void fma2(ull &d, ull a, ull b) {
    asm("fma.rn.f32x2 %0, %1, %2, %0;" : "+l"(d) : "l"(a), "l"(b));
}
__device__ __forceinline__ float2 unpack2(ull v) {
    float2 f; asm("mov.b64 {%0,%1}, %2;" : "=f"(f.x), "=f"(f.y) : "l"(v)); return f;
}

// ================= CSR build =================
__global__ void hist_kernel(const int* __restrict__ ei, int E, int* __restrict__ counts) {
    int e = blockIdx.x * blockDim.x + threadIdx.x;
    if (e < E) atomicAdd(&counts[ei[(size_t)E + e]], 1);
}

__global__ void scan_kernel(const int* __restrict__ counts, int N, int E,
                            int* __restrict__ offs, int* __restrict__ cursor) {
    __shared__ int sm[1024];
    const int tid = threadIdx.x;
    const int chunk = (N + 1023) / 1024;
    const int lo = tid * chunk;
    const int hi = min(lo + chunk, N);
    int s = 0;
    for (int i = lo; i < hi; i++) s += counts[i];
    sm[tid] = s;
    __syncthreads();
    for (int off = 1; off < 1024; off <<= 1) {
        int t = (tid >= off) ? sm[tid - off] : 0;
        __syncthreads();
        sm[tid] += t;
        __syncthreads();
    }
    int run = sm[tid] - s;
    for (int i = lo; i < hi; i++) {
        int c = counts[i];
        offs[i] = run; cursor[i] = run;
        run += c;
    }
    if (tid == 0) offs[N] = E;
}

__global__ void fill_kernel(const int* __restrict__ ei, int E,
                            int* __restrict__ cursor, int* __restrict__ csr_src) {
    int e = blockIdx.x * blockDim.x + threadIdx.x;
    if (e < E) {
        int d = ei[(size_t)E + e];
        int pos = atomicAdd(&cursor[d], 1);
        csr_src[pos] = ei[e];
    }
}

// ================= standalone gather: acc[v] = x[v] + sum_{u in in(v)} x[u] =================
// 256-thread blocks -> reg-limited occupancy ~5 CTAs/SM (40 warps): deep pool of
// independent L2-latency chains. No SMEM, warp per node.
__global__ void gather_kernel(float4* __restrict__ acc, const float4* __restrict__ x,
                              const int* __restrict__ offs, const int* __restrict__ csr,
                              int N) {
    int warp = (blockIdx.x * blockDim.x + threadIdx.x) >> 5;
    int lane = threadIdx.x & 31;
    if (warp >= N) return;
    int lo = offs[warp];
    int hi = offs[warp + 1];
    float4 a = x[(size_t)warp * 32 + lane];
    for (int base = lo; base < hi; base += 32) {
        int cnt = hi - base; if (cnt > 32) cnt = 32;
        int idx = (lane < cnt) ? __ldg(csr + base + lane) : 0;
        int j = 0;
        for (; j + 8 <= cnt; j += 8) {
            int s0 = __shfl_sync(0xffffffffu, idx, j + 0);
            int s1 = __shfl_sync(0xffffffffu, idx, j + 1);
            int s2 = __shfl_sync(0xffffffffu, idx, j + 2);
            int s3 = __shfl_sync(0xffffffffu, idx, j + 3);
            int s4 = __shfl_sync(0xffffffffu, idx, j + 4);
            int s5 = __shfl_sync(0xffffffffu, idx, j + 5);
            int s6 = __shfl_sync(0xffffffffu, idx, j + 6);
            int s7 = __shfl_sync(0xffffffffu, idx, j + 7);
            float4 v0 = __ldg(x + (size_t)s0 * 32 + lane);
            float4 v1 = __ldg(x + (size_t)s1 * 32 + lane);
            float4 v2 = __ldg(x + (size_t)s2 * 32 + lane);
            float4 v3 = __ldg(x + (size_t)s3 * 32 + lane);
            float4 v4 = __ldg(x + (size_t)s4 * 32 + lane);
            float4 v5 = __ldg(x + (size_t)s5 * 32 + lane);
            float4 v6 = __ldg(x + (size_t)s6 * 32 + lane);
            float4 v7 = __ldg(x + (size_t)s7 * 32 + lane);
            a.x += v0.x + v1.x + v2.x + v3.x + v4.x + v5.x + v6.x + v7.x;
            a.y += v0.y + v1.y + v2.y + v3.y + v4.y + v5.y + v6.y + v7.y;
            a.z += v0.z + v1.z + v2.z + v3.z + v4.z + v5.z + v6.z + v7.z;
            a.w += v0.w + v1.w + v2.w + v3.w + v4.w + v5.w + v6.w + v7.w;
        }
        for (; j < cnt; j++) {
            int s = __shfl_sync(0xffffffffu, idx, j);
            float4 v = __ldg(x + (size_t)s * 32 + lane);
            a.x += v.x; a.y += v.y; a.z += v.z; a.w += v.w;
        }
    }
    acc[(size_t)warp * 32 + lane] = a;
}

// ================= MLP: xout = relu(acc@W1+b1)@W2+b2   (or GEMM1-only) =================
// 8 rows/warp, h overwrites rows in place (warp-private region, syncwarp-fenced).
// Crossbar per SM per kq: 16*(16+8)=384 cyc < fma 512 cyc -> fma-bound, 25% slack.
// Work unit = per-WARP 8-row chunk (warps autonomous; fine-grained tail).
// do_gemm2==0 (last layer): write relu(GEMM1) directly; GEMM2 is algebraically
// folded into the per-graph pooling (sum commutes with the linear map).
__global__ void __launch_bounds__(MLP_THREADS, 1) mlp_kernel(
    const float4* __restrict__ acc4,
    const float* __restrict__ W1, const float* __restrict__ b1,
    const float* __restrict__ W2, const float* __restrict__ b2,
    float* __restrict__ xout, int n, int nchunks, int do_gemm2)
{
    extern __shared__ float smem[];
    float* W1s  = smem;                 // 16384 floats (transposed + swizzled)
    float* W2s  = W1s + 16384;          // 16384
    float* rows = W2s + 16384;          // 16 warps * 8 rows * 128 = 16384

    const int tid  = threadIdx.x;
    const int lane = tid & 31;
    const int wid  = tid >> 5;
    float* rows_w  = rows + wid * (ROWS_PER_WARP * 128);

    // ---- stage W1^T, W2^T with XOR swizzle:
    //      element (c,k) at word c*128 + 4*((k>>2) ^ ((c>>2)&31)) + (k&3)
    //      -> w LDS.128 chunk (kq ^ lane): conflict-free (full 5-bit lane XOR) ----
    {
        const float4* w1g = (const float4*)W1;
        const float4* w2g = (const float4*)W2;
        for (int i = tid; i < 4096; i += MLP_THREADS) {
            int k = i >> 5, c4 = i & 31;
            float4 a = w1g[i];
            float4 b = w2g[i];
            int kq = k >> 2, kr = k & 3;
            #pragma unroll
            for (int j = 0; j < 4; j++) {
                int c = 4 * c4 + j;
                int addr = c * 128 + 4 * (kq ^ ((c >> 2) & 31)) + kr;
                float av = (j == 0) ? a.x : (j == 1) ? a.y : (j == 2) ? a.z : a.w;
                float bv = (j == 0) ? b.x : (j == 1) ? b.y : (j == 2) ? b.z : b.w;
                W1s[addr] = av;
                W2s[addr] = bv;
            }
        }
    }
    float bb1[4], bb2[4];
    #pragma unroll
    for (int j = 0; j < 4; j++) { bb1[j] = b1[lane * 4 + j]; bb2[j] = b2[lane * 4 + j]; }
    __syncthreads();   // W visible; only block-wide sync in kernel

    const int warps_total = gridDim.x * (MLP_THREADS / 32);
    for (int c = blockIdx.x * (MLP_THREADS / 32) + wid; c < nchunks; c += warps_total) {
        const int rbase = c * ROWS_PER_WARP;

        // ---- stage 8 rows: independent coalesced loads ----
        #pragma unroll
        for (int r = 0; r < ROWS_PER_WARP; r++) {
            float4 v = (rbase + r < n) ? __ldg(acc4 + (size_t)(rbase + r) * 32 + lane)
                                       : make_float4(0.f, 0.f, 0.f, 0.f);
            ((float4*)rows_w)[r * 32 + lane] = v;
        }
        __syncwarp();

        // ---- GEMM1: acc = rows @ W1 + b1 ----
        ull acc1[ROWS_PER_WARP][4];
        #pragma unroll
        for (int r = 0; r < ROWS_PER_WARP; r++)
            #pragma unroll
            for (int j = 0; j < 4; j++) acc1[r][j] = pack2(bb1[j], 0.f);
        {
            const float* wb = W1s + (lane * 4) * 128;
            #pragma unroll 2
            for (int kq = 0; kq < 32; kq++) {
                const int ch = (kq ^ lane) << 2;
                ulonglong2 w0 = *(const ulonglong2*)(wb + ch);
                ulonglong2 w1 = *(const ulonglong2*)(wb + 128 + ch);
                ulonglong2 w2 = *(const ulonglong2*)(wb + 256 + ch);
                ulonglong2 w3 = *(const ulonglong2*)(wb + 384 + ch);
                #pragma unroll
                for (int r = 0; r < ROWS_PER_WARP; r += 2) {
                    ulonglong2 va = *(const ulonglong2*)(rows_w + r * 128 + kq * 4);
                    ulonglong2 vb = *(const ulonglong2*)(rows_w + (r + 1) * 128 + kq * 4);
                    fma2(acc1[r][0], w0.x, va.x); fma2(acc1[r][1], w1.x, va.x);
                    fma2(acc1[r][2], w2.x, va.x); fma2(acc1[r][3], w3.x, va.x);
                    fma2(acc1[r+1][0], w0.x, vb.x); fma2(acc1[r+1][1], w1.x, vb.x);
                    fma2(acc1[r+1][2], w2.x, vb.x); fma2(acc1[r+1][3], w3.x, vb.x);
                    fma2(acc1[r][0], w0.y, va.y); fma2(acc1[r][1], w1.y, va.y);
                    fma2(acc1[r][2], w2.y, va.y); fma2(acc1[r][3], w3.y, va.y);
                    fma2(acc1[r+1][0], w0.y, vb.y); fma2(acc1[r+1][1], w1.y, vb.y);
                    fma2(acc1[r+1][2], w2.y, vb.y); fma2(acc1[r+1][3], w3.y, vb.y);
                }
            }
        }

        if (do_gemm2) {
            __syncwarp();   // all lanes finished READING rows before overwrite
            #pragma unroll
            for (int r = 0; r < ROWS_PER_WARP; r++) {
                float2 p0 = unpack2(acc1[r][0]);
                float2 p1 = unpack2(acc1[r][1]);
                float2 p2 = unpack2(acc1[r][2]);
                float2 p3 = unpack2(acc1[r][3]);
                float4 h = make_float4(fmaxf(p0.x + p0.y, 0.f), fmaxf(p1.x + p1.y, 0.f),
                                       fmaxf(p2.x + p2.y, 0.f), fmaxf(p3.x + p3.y, 0.f));
                ((float4*)rows_w)[r * 32 + lane] = h;
            }
            __syncwarp();   // h STS -> GEMM2 LDS

            ull acc2[ROWS_PER_WARP][4];
            #pragma unroll
            for (int r = 0; r < ROWS_PER_WARP; r++)
                #pragma unroll
                for (int j = 0; j < 4; j++) acc2[r][j] = pack2(bb2[j], 0.f);
            {
                const float* wb = W2s + (lane * 4) * 128;
                #pragma unroll 2
                for (int kq = 0; kq < 32; kq++) {
                    const int ch = (kq ^ lane) << 2;
                    ulonglong2 w0 = *(const ulonglong2*)(wb + ch);
                    ulonglong2 w1 = *(const ulonglong2*)(wb + 128 + ch);
                    ulonglong2 w2 = *(const ulonglong2*)(wb + 256 + ch);
                    ulonglong2 w3 = *(const ulonglong2*)(wb + 384 + ch);
                    #pragma unroll
                    for (int r = 0; r < ROWS_PER_WARP; r += 2) {
                        ulonglong2 va = *(const ulonglong2*)(rows_w + r * 128 + kq * 4);
                        ulonglong2 vb = *(const ulonglong2*)(rows_w + (r + 1) * 128 + kq * 4);
                        fma2(acc2[r][0], w0.x, va.x); fma2(acc2[r][1], w1.x, va.x);
                        fma2(acc2[r][2], w2.x, va.x); fma2(acc2[r][3], w3.x, va.x);
                        fma2(acc2[r+1][0], w0.x, vb.x); fma2(acc2[r+1][1], w1.x, vb.x);
                        fma2(acc2[r+1][2], w2.x, vb.x); fma2(acc2[r+1][3], w3.x, vb.x);
                        fma2(acc2[r][0], w0.y, va.y); fma2(acc2[r][1], w1.y, va.y);
                        fma2(acc2[r][2], w2.y, va.y); fma2(acc2[r][3], w3.y, va.y);
                        fma2(acc2[r+1][0], w0.y, vb.y); fma2(acc2[r+1][1], w1.y, vb.y);
                        fma2(acc2[r+1][2], w2.y, vb.y); fma2(acc2[r+1][3], w3.y, vb.y);
                    }
                }
            }
            #pragma unroll
            for (int r = 0; r < ROWS_PER_WARP; r++) {
                int row = rbase + r;
                if (row < n) {
                    float2 p0 = unpack2(acc2[r][0]);
                    float2 p1 = unpack2(acc2[r][1]);
                    float2 p2 = unpack2(acc2[r][2]);
                    float2 p3 = unpack2(acc2[r][3]);
                    *(float4*)(xout + (size_t)row * 128 + lane * 4) =
                        make_float4(p0.x + p0.y, p1.x + p1.y, p2.x + p2.y, p3.x + p3.y);
                }
            }
        } else {
            // last layer: write h = relu(GEMM1) directly; GEMM2 folded into pooling
            #pragma unroll
            for (int r = 0; r < ROWS_PER_WARP; r++) {
                int row = rbase + r;
                if (row < n) {
                    float2 p0 = unpack2(acc1[r][0]);
                    float2 p1 = unpack2(acc1[r][1]);
                    float2 p2 = unpack2(acc1[r][2]);
                    float2 p3 = unpack2(acc1[r][3]);
                    *(float4*)(xout + (size_t)row * 128 + lane * 4) =
                        make_float4(fmaxf(p0.x + p0.y, 0.f), fmaxf(p1.x + p1.y, 0.f),
                                    fmaxf(p2.x + p2.y, 0.f), fmaxf(p3.x + p3.y, 0.f));
                }
            }
        }
        __syncwarp();   // all reads of rows_w done before next chunk's staging
    }
}

// ================= pooling + folded final GEMM =================
__device__ __forceinline__ int lower_bound_i(const int* __restrict__ a, int lo, int hi, int v) {
    while (lo < hi) {
        int m = (lo + hi) >> 1;
        if (a[m] < v) lo = m + 1; else hi = m;
    }
    return lo;
}

__global__ void pool_kernel(float* __restrict__ pool, int* __restrict__ cnt,
                            const float* __restrict__ hf,
                            const int* __restrict__ batch, int n) {
    const int g = blockIdx.x;
    const int j = threadIdx.x;
    int lo = lower_bound_i(batch, 0, n, g);
    int hi = lower_bound_i(batch, lo, n, g + 1);
    float s0 = 0.f, s1 = 0.f, s2 = 0.f, s3 = 0.f;
    int r = lo;
    for (; r + 4 <= hi; r += 4) {
        s0 += hf[(size_t)(r + 0) * D + j];
        s1 += hf[(size_t)(r + 1) * D + j];
        s2 += hf[(size_t)(r + 2) * D + j];
        s3 += hf[(size_t)(r + 3) * D + j];
    }
    for (; r < hi; r++) s0 += hf[(size_t)r * D + j];
    pool[(size_t)g * D + j] = (s0 + s1) + (s2 + s3);
    if (j == 0) cnt[g] = hi - lo;
}

// out[g][c] = sum_k pool[g][k] * W2[k][c] + cnt[g] * b2[c]
__global__ void finish_kernel(float* __restrict__ out,
                              const float* __restrict__ pool, const int* __restrict__ cnt,
                              const float* __restrict__ W2, const float* __restrict__ b2) {
    __shared__ float P[D];
    const int g = blockIdx.x;
    const int c = threadIdx.x;
    P[c] = pool[(size_t)g * D + c];
    __syncthreads();
    float s = (float)cnt[g] * b2[c];
    #pragma unroll 8
    for (int k = 0; k < D; k++) s += P[k] * W2[k * D + c];
    out[(size_t)g * D + c] = s;
}

// ================= launch =================
extern "C" void kernel_launch(void* const* d_in, const int* in_sizes, int n_in,
                              void* d_out, int out_size) {
    const float* x   = (const float*)d_in[0];
    const float* W1  = (const float*)d_in[1];
    const float* b1  = (const float*)d_in[2];
    const float* W2  = (const float*)d_in[3];
    const float* b2  = (const float*)d_in[4];
    const int* ei    = (const int*)d_in[5];
    const int* bat   = (const int*)d_in[6];
    float* out       = (float*)d_out;

    const int N = in_sizes[0] / D;
    const int E = in_sizes[5] / 2;
    const int n_layers = in_sizes[1] / (D * D);
    const int n_graphs = out_size / D;

    float *acc, *xA, *xB, *pool;
    int *counts, *offs, *cursor, *csr, *cnt;
    cudaGetSymbolAddress((void**)&acc, g_acc);
    cudaGetSymbolAddress((void**)&xA, g_xA);
    cudaGetSymbolAddress((void**)&xB, g_xB);
    cudaGetSymbolAddress((void**)&counts, g_counts);
    cudaGetSymbolAddress((void**)&offs, g_offs);
    cudaGetSymbolAddress((void**)&cursor, g_cursor);
    cudaGetSymbolAddress((void**)&csr, g_csr_src);
    cudaGetSymbolAddress((void**)&pool, g_pool);
    cudaGetSymbolAddress((void**)&cnt, g_cnt);

    const int smem_bytes = 16384 * 3 * 4;  // 196608: W1s + W2s + rows
    cudaFuncSetAttribute(mlp_kernel, cudaFuncAttributeMaxDynamicSharedMemorySize, smem_bytes);

    // ---- CSR build ----
    cudaMemsetAsync(counts, 0, (size_t)N * sizeof(int), 0);
    hist_kernel<<<(E + 255) / 256, 256>>>(ei, E, counts);      // launch 1
    scan_kernel<<<1, 1024>>>(counts, N, E, offs, cursor);      // launch 2
    fill_kernel<<<(E + 255) / 256, 256>>>(ei, E, cursor, csr); // launch 3

    // ---- layers (launch 4 = gather layer 0, profiled) ----
    const int nchunks = (N + ROWS_PER_WARP - 1) / ROWS_PER_WARP;
    const int gather_blocks = (N * 32 + 255) / 256;
    const float* xin = x;
    float* bufs[2] = { xA, xB };

    for (int l = 0; l < n_layers; l++) {
        int last = (l == n_layers - 1);
        gather_kernel<<<gather_blocks, 256>>>((float4*)acc, (const float4*)xin,
                                              offs, csr, N);
        mlp_kernel<<<148, MLP_THREADS, smem_bytes>>>(
            (const float4*)acc,
            W1 + (size_t)l * D * D, b1 + (size_t)l * D,
            W2 + (size_t)l * D * D, b2 + (size_t)l * D,
            bufs[l & 1], N, nchunks, last ? 0 : 1);
        xin = bufs[l & 1];
    }

    // ---- pooled readout + folded final GEMM2 ----
    const float* W2l = W2 + (size_t)(n_layers - 1) * D * D;
    const float* b2l = b2 + (size_t)(n_layers - 1) * D;
    pool_kernel<<<n_graphs, D>>>(pool, cnt, xin, bat, N);
    finish_kernel<<<n_graphs, D>>>(out, pool, cnt, W2l, b2l);
}

// round 14
// speedup vs baseline: 3.6374x; 1.1672x over previous
#include <cuda_runtime.h>
#include <cuda_bf16.h>
#include <cstdint>

#define D 128
#define MLP_THREADS 512
#define ROWS_PER_WARP 8

typedef unsigned long long ull;

// -------- scratch (no cudaMalloc allowed) --------
#define MAX_NODES 100000
#define MAX_EDGES 1600000
#define N_GRAPHS_MAX 128
__device__ float g_acc[(size_t)MAX_NODES * D];
__device__ float g_xA[(size_t)MAX_NODES * D];
__device__ float g_xB[(size_t)MAX_NODES * D];
__device__ int   g_counts[MAX_NODES];
__device__ int   g_offs[MAX_NODES + 1];
__device__ int   g_cursor[MAX_NODES];
__device__ int   g_csr_src[MAX_EDGES];
__device__ float g_pool[N_GRAPHS_MAX * D];
__device__ int   g_cnt[N_GRAPHS_MAX];
__device__ float g_W12[2 * D * D];   // fused W2_l @ W1_{l+1}
__device__ float g_u[2 * D];         // b2_l @ W1_{l+1}

// -------- packed fp32x2 helpers (Blackwell FFMA2) --------
__device__ __forceinline__ ull pack2(float lo, float hi) {
    ull r; asm("mov.b64 %0, {%1,%2};" : "=l"(r) : "f"(lo), "f"(hi)); return r;
}
__device__ __forceinline__ void fma2(ull &d, ull a, ull b) {
    asm("fma.rn.f32x2 %0, %1, %2, %0;" : "+l"(d) : "l"(a), "l"(b));
}
__device__ __forceinline__ float2 unpack2(ull v) {
    float2 f; asm("mov.b64 {%0,%1}, %2;" : "=f"(f.x), "=f"(f.y) : "l"(v)); return f;
}

// ================= CSR build =================
__global__ void hist_kernel(const int* __restrict__ ei, int E, int* __restrict__ counts) {
    int e = blockIdx.x * blockDim.x + threadIdx.x;
    if (e < E) atomicAdd(&counts[ei[(size_t)E + e]], 1);
}

__global__ void scan_kernel(const int* __restrict__ counts, int N, int E,
                            int* __restrict__ offs, int* __restrict__ cursor) {
    __shared__ int sm[1024];
    const int tid = threadIdx.x;
    const int chunk = (N + 1023) / 1024;
    const int lo = tid * chunk;
    const int hi = min(lo + chunk, N);
    int s = 0;
    for (int i = lo; i < hi; i++) s += counts[i];
    sm[tid] = s;
    __syncthreads();
    for (int off = 1; off < 1024; off <<= 1) {
        int t = (tid >= off) ? sm[tid - off] : 0;
        __syncthreads();
        sm[tid] += t;
        __syncthreads();
    }
    int run = sm[tid] - s;
    for (int i = lo; i < hi; i++) {
        int c = counts[i];
        offs[i] = run; cursor[i] = run;
        run += c;
    }
    if (tid == 0) offs[N] = E;
}

__global__ void fill_kernel(const int* __restrict__ ei, int E,
                            int* __restrict__ cursor, int* __restrict__ csr_src) {
    int e = blockIdx.x * blockDim.x + threadIdx.x;
    if (e < E) {
        int d = ei[(size_t)E + e];
        int pos = atomicAdd(&cursor[d], 1);
        csr_src[pos] = ei[e];
    }
}

// ================= fused-weight precompute =================
// block k<128:  W12[k][c] = sum_j W2[k][j] * W1n[j][c]
// block k==128: u[c]      = sum_j b2[j]   * W1n[j][c]
__global__ void wmul_kernel(float* __restrict__ W12, float* __restrict__ u,
                            const float* __restrict__ W2, const float* __restrict__ W1n,
                            const float* __restrict__ b2) {
    __shared__ float row[D];
    const int k = blockIdx.x;
    const int c = threadIdx.x;
    row[c] = (k < D) ? W2[k * D + c] : b2[c];
    __syncthreads();
    float s = 0.f;
    #pragma unroll 8
    for (int j = 0; j < D; j++) s += row[j] * W1n[j * D + c];
    if (k < D) W12[k * D + c] = s;
    else       u[c] = s;
}

// ================= gather (unchanged, proven 72us) =================
__global__ void gather_kernel(float4* __restrict__ acc, const float4* __restrict__ x,
                              const int* __restrict__ offs, const int* __restrict__ csr,
                              int N) {
    int warp = (blockIdx.x * blockDim.x + threadIdx.x) >> 5;
    int lane = threadIdx.x & 31;
    if (warp >= N) return;
    int lo = offs[warp];
    int hi = offs[warp + 1];
    float4 a = x[(size_t)warp * 32 + lane];
    for (int base = lo; base < hi; base += 32) {
        int cnt = hi - base; if (cnt > 32) cnt = 32;
        int idx = (lane < cnt) ? __ldg(csr + base + lane) : 0;
        int j = 0;
        for (; j + 8 <= cnt; j += 8) {
            int s0 = __shfl_sync(0xffffffffu, idx, j + 0);
            int s1 = __shfl_sync(0xffffffffu, idx, j + 1);
            int s2 = __shfl_sync(0xffffffffu, idx, j + 2);
            int s3 = __shfl_sync(0xffffffffu, idx, j + 3);
            int s4 = __shfl_sync(0xffffffffu, idx, j + 4);
            int s5 = __shfl_sync(0xffffffffu, idx, j + 5);
            int s6 = __shfl_sync(0xffffffffu, idx, j + 6);
            int s7 = __shfl_sync(0xffffffffu, idx, j + 7);
            float4 v0 = __ldg(x + (size_t)s0 * 32 + lane);
            float4 v1 = __ldg(x + (size_t)s1 * 32 + lane);
            float4 v2 = __ldg(x + (size_t)s2 * 32 + lane);
            float4 v3 = __ldg(x + (size_t)s3 * 32 + lane);
            float4 v4 = __ldg(x + (size_t)s4 * 32 + lane);
            float4 v5 = __ldg(x + (size_t)s5 * 32 + lane);
            float4 v6 = __ldg(x + (size_t)s6 * 32 + lane);
            float4 v7 = __ldg(x + (size_t)s7 * 32 + lane);
            a.x += v0.x + v1.x + v2.x + v3.x + v4.x + v5.x + v6.x + v7.x;
            a.y += v0.y + v1.y + v2.y + v3.y + v4.y + v5.y + v6.y + v7.y;
            a.z += v0.z + v1.z + v2.z + v3.z + v4.z + v5.z + v6.z + v7.z;
            a.w += v0.w + v1.w + v2.w + v3.w + v4.w + v5.w + v6.w + v7.w;
        }
        for (; j < cnt; j++) {
            int s = __shfl_sync(0xffffffffu, idx, j);
            float4 v = __ldg(x + (size_t)s * 32 + lane);
            a.x += v.x; a.y += v.y; a.z += v.z; a.w += v.w;
        }
    }
    acc[(size_t)warp * 32 + lane] = a;
}

// ================= single-GEMM layer: h = relu(acc@W + b + (1+deg)*u) =================
// R12 GEMM core (proven conflict-free XOR swizzle, warp-autonomous 8-row chunks),
// single GEMM only. The second GEMM of each GIN MLP is algebraically folded into
// the NEXT layer's weight (W12 = W2@W1') with a degree-scaled bias correction,
// since gather is the linear op S = I + A and commutes with the affine map.
__global__ void __launch_bounds__(MLP_THREADS, 1) mlp_single_kernel(
    const float4* __restrict__ acc4,
    const float* __restrict__ W, const float* __restrict__ b,
    const float* __restrict__ u, int has_u,
    const int* __restrict__ deg,
    float* __restrict__ xout, int n, int nchunks)
{
    extern __shared__ float smem[];
    float* Ws   = smem;                 // 16384 floats (transposed + swizzled)
    float* rows = Ws + 16384;           // 16 warps * 8 rows * 128 = 16384

    const int tid  = threadIdx.x;
    const int lane = tid & 31;
    const int wid  = tid >> 5;
    float* rows_w  = rows + wid * (ROWS_PER_WARP * 128);

    // ---- stage W^T with XOR swizzle:
    //      element (c,k) at word c*128 + 4*((k>>2) ^ ((c>>2)&31)) + (k&3)
    //      -> w LDS.128 chunk (kq ^ lane): conflict-free (full 5-bit lane XOR) ----
    {
        const float4* wg = (const float4*)W;
        for (int i = tid; i < 4096; i += MLP_THREADS) {
            int k = i >> 5, c4 = i & 31;
            float4 a = wg[i];
            int kq = k >> 2, kr = k & 3;
            #pragma unroll
            for (int j = 0; j < 4; j++) {
                int c = 4 * c4 + j;
                int addr = c * 128 + 4 * (kq ^ ((c >> 2) & 31)) + kr;
                float av = (j == 0) ? a.x : (j == 1) ? a.y : (j == 2) ? a.z : a.w;
                Ws[addr] = av;
            }
        }
    }
    float bb[4], uu[4];
    #pragma unroll
    for (int j = 0; j < 4; j++) {
        bb[j] = b[lane * 4 + j];
        uu[j] = has_u ? u[lane * 4 + j] : 0.f;
    }
    __syncthreads();   // W visible; only block-wide sync in kernel

    const int warps_total = gridDim.x * (MLP_THREADS / 32);
    for (int c = blockIdx.x * (MLP_THREADS / 32) + wid; c < nchunks; c += warps_total) {
        const int rbase = c * ROWS_PER_WARP;

        // ---- stage 8 rows: independent coalesced loads ----
        #pragma unroll
        for (int r = 0; r < ROWS_PER_WARP; r++) {
            float4 v = (rbase + r < n) ? __ldg(acc4 + (size_t)(rbase + r) * 32 + lane)
                                       : make_float4(0.f, 0.f, 0.f, 0.f);
            ((float4*)rows_w)[r * 32 + lane] = v;
        }
        __syncwarp();

        // ---- GEMM: acc1 = rows @ W + b ----
        ull acc1[ROWS_PER_WARP][4];
        #pragma unroll
        for (int r = 0; r < ROWS_PER_WARP; r++)
            #pragma unroll
            for (int j = 0; j < 4; j++) acc1[r][j] = pack2(bb[j], 0.f);
        {
            const float* wb = Ws + (lane * 4) * 128;
            #pragma unroll 2
            for (int kq = 0; kq < 32; kq++) {
                const int ch = (kq ^ lane) << 2;
                ulonglong2 w0 = *(const ulonglong2*)(wb + ch);
                ulonglong2 w1 = *(const ulonglong2*)(wb + 128 + ch);
                ulonglong2 w2 = *(const ulonglong2*)(wb + 256 + ch);
                ulonglong2 w3 = *(const ulonglong2*)(wb + 384 + ch);
                #pragma unroll
                for (int r = 0; r < ROWS_PER_WARP; r += 2) {
                    ulonglong2 va = *(const ulonglong2*)(rows_w + r * 128 + kq * 4);
                    ulonglong2 vb = *(const ulonglong2*)(rows_w + (r + 1) * 128 + kq * 4);
                    fma2(acc1[r][0], w0.x, va.x); fma2(acc1[r][1], w1.x, va.x);
                    fma2(acc1[r][2], w2.x, va.x); fma2(acc1[r][3], w3.x, va.x);
                    fma2(acc1[r+1][0], w0.x, vb.x); fma2(acc1[r+1][1], w1.x, vb.x);
                    fma2(acc1[r+1][2], w2.x, vb.x); fma2(acc1[r+1][3], w3.x, vb.x);
                    fma2(acc1[r][0], w0.y, va.y); fma2(acc1[r][1], w1.y, va.y);
                    fma2(acc1[r][2], w2.y, va.y); fma2(acc1[r][3], w3.y, va.y);
                    fma2(acc1[r+1][0], w0.y, vb.y); fma2(acc1[r+1][1], w1.y, vb.y);
                    fma2(acc1[r+1][2], w2.y, vb.y); fma2(acc1[r+1][3], w3.y, vb.y);
                }
            }
        }

        // ---- epilogue: h = relu(sum + (1+deg)*u) ----
        #pragma unroll
        for (int r = 0; r < ROWS_PER_WARP; r++) {
            int row = rbase + r;
            if (row < n) {
                float sc = has_u ? (1.f + (float)deg[row]) : 0.f;
                float2 p0 = unpack2(acc1[r][0]);
                float2 p1 = unpack2(acc1[r][1]);
                float2 p2 = unpack2(acc1[r][2]);
                float2 p3 = unpack2(acc1[r][3]);
                *(float4*)(xout + (size_t)row * 128 + lane * 4) = make_float4(
                    fmaxf(p0.x + p0.y + sc * uu[0], 0.f),
                    fmaxf(p1.x + p1.y + sc * uu[1], 0.f),
                    fmaxf(p2.x + p2.y + sc * uu[2], 0.f),
                    fmaxf(p3.x + p3.y + sc * uu[3], 0.f));
            }
        }
        __syncwarp();   // rows_w reads done before next chunk's staging
    }
}

// ================= pooling + folded final GEMM (unchanged) =================
__device__ __forceinline__ int lower_bound_i(const int* __restrict__ a, int lo, int hi, int v) {
    while (lo < hi) {
        int m = (lo + hi) >> 1;
        if (a[m] < v) lo = m + 1; else hi = m;
    }
    return lo;
}

__global__ void pool_kernel(float* __restrict__ pool, int* __restrict__ cnt,
                            const float* __restrict__ hf,
                            const int* __restrict__ batch, int n) {
    const int g = blockIdx.x;
    const int j = threadIdx.x;
    int lo = lower_bound_i(batch, 0, n, g);
    int hi = lower_bound_i(batch, lo, n, g + 1);
    float s0 = 0.f, s1 = 0.f, s2 = 0.f, s3 = 0.f;
    int r = lo;
    for (; r + 4 <= hi; r += 4) {
        s0 += hf[(size_t)(r + 0) * D + j];
        s1 += hf[(size_t)(r + 1) * D + j];
        s2 += hf[(size_t)(r + 2) * D + j];
        s3 += hf[(size_t)(r + 3) * D + j];
    }
    for (; r < hi; r++) s0 += hf[(size_t)r * D + j];
    pool[(size_t)g * D + j] = (s0 + s1) + (s2 + s3);
    if (j == 0) cnt[g] = hi - lo;
}

__global__ void finish_kernel(float* __restrict__ out,
                              const float* __restrict__ pool, const int* __restrict__ cnt,
                              const float* __restrict__ W2, const float* __restrict__ b2) {
    __shared__ float P[D];
    const int g = blockIdx.x;
    const int c = threadIdx.x;
    P[c] = pool[(size_t)g * D + c];
    __syncthreads();
    float s = (float)cnt[g] * b2[c];
    #pragma unroll 8
    for (int k = 0; k < D; k++) s += P[k] * W2[k * D + c];
    out[(size_t)g * D + c] = s;
}

// ================= launch =================
extern "C" void kernel_launch(void* const* d_in, const int* in_sizes, int n_in,
                              void* d_out, int out_size) {
    const float* x   = (const float*)d_in[0];
    const float* W1  = (const float*)d_in[1];
    const float* b1  = (const float*)d_in[2];
    const float* W2  = (const float*)d_in[3];
    const float* b2  = (const float*)d_in[4];
    const int* ei    = (const int*)d_in[5];
    const int* bat   = (const int*)d_in[6];
    float* out       = (float*)d_out;

    const int N = in_sizes[0] / D;
    const int E = in_sizes[5] / 2;
    const int n_layers = in_sizes[1] / (D * D);
    const int n_graphs = out_size / D;

    float *acc, *xA, *xB, *pool, *W12, *uvec;
    int *counts, *offs, *cursor, *csr, *cnt;
    cudaGetSymbolAddress((void**)&acc, g_acc);
    cudaGetSymbolAddress((void**)&xA, g_xA);
    cudaGetSymbolAddress((void**)&xB, g_xB);
    cudaGetSymbolAddress((void**)&counts, g_counts);
    cudaGetSymbolAddress((void**)&offs, g_offs);
    cudaGetSymbolAddress((void**)&cursor, g_cursor);
    cudaGetSymbolAddress((void**)&csr, g_csr_src);
    cudaGetSymbolAddress((void**)&pool, g_pool);
    cudaGetSymbolAddress((void**)&cnt, g_cnt);
    cudaGetSymbolAddress((void**)&W12, g_W12);
    cudaGetSymbolAddress((void**)&uvec, g_u);

    const int smem_bytes = 16384 * 2 * 4;  // 131072: Ws + rows
    cudaFuncSetAttribute(mlp_single_kernel, cudaFuncAttributeMaxDynamicSharedMemorySize, smem_bytes);

    // ---- CSR build ----
    cudaMemsetAsync(counts, 0, (size_t)N * sizeof(int), 0);
    hist_kernel<<<(E + 255) / 256, 256>>>(ei, E, counts);
    scan_kernel<<<1, 1024>>>(counts, N, E, offs, cursor);
    fill_kernel<<<(E + 255) / 256, 256>>>(ei, E, cursor, csr);

    // ---- fused-weight precompute: W12_l = W2_l @ W1_{l+1}, u_l = b2_l @ W1_{l+1} ----
    for (int l = 0; l + 1 < n_layers; l++) {
        wmul_kernel<<<D + 1, D>>>(W12 + (size_t)l * D * D, uvec + (size_t)l * D,
                                  W2 + (size_t)l * D * D, W1 + (size_t)(l + 1) * D * D,
                                  b2 + (size_t)l * D);
    }

    // ---- layers: gather + single fused GEMM each ----
    const int nchunks = (N + ROWS_PER_WARP - 1) / ROWS_PER_WARP;
    const int gather_blocks = (N * 32 + 255) / 256;
    const float* xin = x;
    float* bufs[2] = { xA, xB };

    for (int l = 0; l < n_layers; l++) {
        gather_kernel<<<gather_blocks, 256>>>((float4*)acc, (const float4*)xin,
                                              offs, csr, N);
        const float* Wg = (l == 0) ? W1 : (W12 + (size_t)(l - 1) * D * D);
        const float* bg = b1 + (size_t)l * D;
        const float* ug = (l == 0) ? (const float*)nullptr : (uvec + (size_t)(l - 1) * D);
        mlp_single_kernel<<<148, MLP_THREADS, smem_bytes>>>(
            (const float4*)acc, Wg, bg, ug, (l == 0) ? 0 : 1, counts,
            bufs[l & 1], N, nchunks);
        xin = bufs[l & 1];
    }

    // ---- pooled readout + folded final GEMM2 (fp32 exact) ----
    const float* W2l = W2 + (size_t)(n_layers - 1) * D * D;
    const float* b2l = b2 + (size_t)(n_layers - 1) * D;
    pool_kernel<<<n_graphs, D>>>(pool, cnt, xin, bat, N);
    finish_kernel<<<n_graphs, D>>>(out, pool, cnt, W2l, b2l);
}

// round 15
// speedup vs baseline: 3.7799x; 1.0392x over previous
#include <cuda_runtime.h>
#include <cuda_bf16.h>
#include <cstdint>

#define D 128
#define MLP_THREADS 384
#define MLP_WARPS 12
#define ROWS_PER_WARP 4

typedef unsigned long long ull;

// -------- scratch (no cudaMalloc allowed) --------
#define MAX_NODES 100000
#define MAX_EDGES 1600000
#define N_GRAPHS_MAX 128
__device__ float g_acc[(size_t)MAX_NODES * D];
__device__ float g_xA[(size_t)MAX_NODES * D];
__device__ float g_xB[(size_t)MAX_NODES * D];
__device__ int   g_counts[MAX_NODES];
__device__ int   g_offs[MAX_NODES + 1];
__device__ int   g_cursor[MAX_NODES];
__device__ int   g_csr_src[MAX_EDGES];
__device__ float g_pool[N_GRAPHS_MAX * D];
__device__ int   g_cnt[N_GRAPHS_MAX];
__device__ float g_W12[2 * D * D];   // fused W2_l @ W1_{l+1}
__device__ float g_u[2 * D];         // b2_l @ W1_{l+1}

// -------- packed fp32x2 helpers (Blackwell FFMA2) --------
__device__ __forceinline__ ull pack2(float lo, float hi) {
    ull r; asm("mov.b64 %0, {%1,%2};" : "=l"(r) : "f"(lo), "f"(hi)); return r;
}
__device__ __forceinline__ void fma2(ull &d, ull a, ull b) {
    asm("fma.rn.f32x2 %0, %1, %2, %0;" : "+l"(d) : "l"(a), "l"(b));
}
__device__ __forceinline__ float2 unpack2(ull v) {
    float2 f; asm("mov.b64 {%0,%1}, %2;" : "=f"(f.x), "=f"(f.y) : "l"(v)); return f;
}

// ================= CSR build =================
__global__ void hist_kernel(const int* __restrict__ ei, int E, int* __restrict__ counts) {
    int e = blockIdx.x * blockDim.x + threadIdx.x;
    if (e < E) atomicAdd(&counts[ei[(size_t)E + e]], 1);
}

__global__ void scan_kernel(const int* __restrict__ counts, int N, int E,
                            int* __restrict__ offs, int* __restrict__ cursor) {
    __shared__ int sm[1024];
    const int tid = threadIdx.x;
    const int chunk = (N + 1023) / 1024;
    const int lo = tid * chunk;
    const int hi = min(lo + chunk, N);
    int s = 0;
    for (int i = lo; i < hi; i++) s += counts[i];
    sm[tid] = s;
    __syncthreads();
    for (int off = 1; off < 1024; off <<= 1) {
        int t = (tid >= off) ? sm[tid - off] : 0;
        __syncthreads();
        sm[tid] += t;
        __syncthreads();
    }
    int run = sm[tid] - s;
    for (int i = lo; i < hi; i++) {
        int c = counts[i];
        offs[i] = run; cursor[i] = run;
        run += c;
    }
    if (tid == 0) offs[N] = E;
}

__global__ void fill_kernel(const int* __restrict__ ei, int E,
                            int* __restrict__ cursor, int* __restrict__ csr_src) {
    int e = blockIdx.x * blockDim.x + threadIdx.x;
    if (e < E) {
        int d = ei[(size_t)E + e];
        int pos = atomicAdd(&cursor[d], 1);
        csr_src[pos] = ei[e];
    }
}

// ================= fused-weight precompute =================
__global__ void wmul_kernel(float* __restrict__ W12, float* __restrict__ u,
                            const float* __restrict__ W2, const float* __restrict__ W1n,
                            const float* __restrict__ b2) {
    __shared__ float row[D];
    const int k = blockIdx.x;
    const int c = threadIdx.x;
    row[c] = (k < D) ? W2[k * D + c] : b2[c];
    __syncthreads();
    float s = 0.f;
    #pragma unroll 8
    for (int j = 0; j < D; j++) s += row[j] * W1n[j * D + c];
    if (k < D) W12[k * D + c] = s;
    else       u[c] = s;
}

// ================= gather (unchanged, at LTS throughput cap) =================
__global__ void gather_kernel(float4* __restrict__ acc, const float4* __restrict__ x,
                              const int* __restrict__ offs, const int* __restrict__ csr,
                              int N) {
    int warp = (blockIdx.x * blockDim.x + threadIdx.x) >> 5;
    int lane = threadIdx.x & 31;
    if (warp >= N) return;
    int lo = offs[warp];
    int hi = offs[warp + 1];
    float4 a = x[(size_t)warp * 32 + lane];
    for (int base = lo; base < hi; base += 32) {
        int cnt = hi - base; if (cnt > 32) cnt = 32;
        int idx = (lane < cnt) ? __ldg(csr + base + lane) : 0;
        int j = 0;
        for (; j + 8 <= cnt; j += 8) {
            int s0 = __shfl_sync(0xffffffffu, idx, j + 0);
            int s1 = __shfl_sync(0xffffffffu, idx, j + 1);
            int s2 = __shfl_sync(0xffffffffu, idx, j + 2);
            int s3 = __shfl_sync(0xffffffffu, idx, j + 3);
            int s4 = __shfl_sync(0xffffffffu, idx, j + 4);
            int s5 = __shfl_sync(0xffffffffu, idx, j + 5);
            int s6 = __shfl_sync(0xffffffffu, idx, j + 6);
            int s7 = __shfl_sync(0xffffffffu, idx, j + 7);
            float4 v0 = __ldg(x + (size_t)s0 * 32 + lane);
            float4 v1 = __ldg(x + (size_t)s1 * 32 + lane);
            float4 v2 = __ldg(x + (size_t)s2 * 32 + lane);
            float4 v3 = __ldg(x + (size_t)s3 * 32 + lane);
            float4 v4 = __ldg(x + (size_t)s4 * 32 + lane);
            float4 v5 = __ldg(x + (size_t)s5 * 32 + lane);
            float4 v6 = __ldg(x + (size_t)s6 * 32 + lane);
            float4 v7 = __ldg(x + (size_t)s7 * 32 + lane);
            a.x += v0.x + v1.x + v2.x + v3.x + v4.x + v5.x + v6.x + v7.x;
            a.y += v0.y + v1.y + v2.y + v3.y + v4.y + v5.y + v6.y + v7.y;
            a.z += v0.z + v1.z + v2.z + v3.z + v4.z + v5.z + v6.z + v7.z;
            a.w += v0.w + v1.w + v2.w + v3.w + v4.w + v5.w + v6.w + v7.w;
        }
        for (; j < cnt; j++) {
            int s = __shfl_sync(0xffffffffu, idx, j);
            float4 v = __ldg(x + (size_t)s * 32 + lane);
            a.x += v.x; a.y += v.y; a.z += v.z; a.w += v.w;
        }
    }
    acc[(size_t)warp * 32 + lane] = a;
}

// ================= single-GEMM layer: h = relu(acc@W + b + (1+deg)*u) =================
// 2 CTAs/SM (384 threads, 4 rows/warp, 88KB SMEM, <=85 regs): 24 warps/SM to
// cover LDS->FFMA2 latency. GEMM core keeps the proven conflict-free XOR swizzle.
__global__ void __launch_bounds__(MLP_THREADS, 2) mlp_single_kernel(
    const float4* __restrict__ acc4,
    const float* __restrict__ W, const float* __restrict__ b,
    const float* __restrict__ u, int has_u,
    const int* __restrict__ deg,
    float* __restrict__ xout, int n, int nchunks)
{
    extern __shared__ float smem[];
    float* Ws   = smem;                           // 16384 floats
    float* rows = Ws + 16384;                     // 12 warps * 4 rows * 128 = 6144

    const int tid  = threadIdx.x;
    const int lane = tid & 31;
    const int wid  = tid >> 5;
    float* rows_w  = rows + wid * (ROWS_PER_WARP * 128);

    // ---- stage W^T with XOR swizzle (conflict-free LDS.128 k-quads) ----
    {
        const float4* wg = (const float4*)W;
        for (int i = tid; i < 4096; i += MLP_THREADS) {
            int k = i >> 5, c4 = i & 31;
            float4 a = wg[i];
            int kq = k >> 2, kr = k & 3;
            #pragma unroll
            for (int j = 0; j < 4; j++) {
                int c = 4 * c4 + j;
                int addr = c * 128 + 4 * (kq ^ ((c >> 2) & 31)) + kr;
                float av = (j == 0) ? a.x : (j == 1) ? a.y : (j == 2) ? a.z : a.w;
                Ws[addr] = av;
            }
        }
    }
    float bb[4], uu[4];
    #pragma unroll
    for (int j = 0; j < 4; j++) {
        bb[j] = b[lane * 4 + j];
        uu[j] = has_u ? u[lane * 4 + j] : 0.f;
    }
    __syncthreads();   // W visible; only block-wide sync in kernel

    const int warps_total = gridDim.x * MLP_WARPS;
    for (int c = blockIdx.x * MLP_WARPS + wid; c < nchunks; c += warps_total) {
        const int rbase = c * ROWS_PER_WARP;

        // ---- stage 4 rows: independent coalesced loads ----
        #pragma unroll
        for (int r = 0; r < ROWS_PER_WARP; r++) {
            float4 v = (rbase + r < n) ? __ldg(acc4 + (size_t)(rbase + r) * 32 + lane)
                                       : make_float4(0.f, 0.f, 0.f, 0.f);
            ((float4*)rows_w)[r * 32 + lane] = v;
        }
        __syncwarp();

        // ---- GEMM: acc1 = rows @ W + b ----
        ull acc1[ROWS_PER_WARP][4];
        #pragma unroll
        for (int r = 0; r < ROWS_PER_WARP; r++)
            #pragma unroll
            for (int j = 0; j < 4; j++) acc1[r][j] = pack2(bb[j], 0.f);
        {
            const float* wb = Ws + (lane * 4) * 128;
            #pragma unroll 4
            for (int kq = 0; kq < 32; kq++) {
                const int ch = (kq ^ lane) << 2;
                ulonglong2 w0 = *(const ulonglong2*)(wb + ch);
                ulonglong2 w1 = *(const ulonglong2*)(wb + 128 + ch);
                ulonglong2 w2 = *(const ulonglong2*)(wb + 256 + ch);
                ulonglong2 w3 = *(const ulonglong2*)(wb + 384 + ch);
                ulonglong2 va = *(const ulonglong2*)(rows_w + 0 * 128 + kq * 4);
                ulonglong2 vb = *(const ulonglong2*)(rows_w + 1 * 128 + kq * 4);
                ulonglong2 vc = *(const ulonglong2*)(rows_w + 2 * 128 + kq * 4);
                ulonglong2 vd = *(const ulonglong2*)(rows_w + 3 * 128 + kq * 4);
                fma2(acc1[0][0], w0.x, va.x); fma2(acc1[0][1], w1.x, va.x);
                fma2(acc1[0][2], w2.x, va.x); fma2(acc1[0][3], w3.x, va.x);
                fma2(acc1[1][0], w0.x, vb.x); fma2(acc1[1][1], w1.x, vb.x);
                fma2(acc1[1][2], w2.x, vb.x); fma2(acc1[1][3], w3.x, vb.x);
                fma2(acc1[2][0], w0.x, vc.x); fma2(acc1[2][1], w1.x, vc.x);
                fma2(acc1[2][2], w2.x, vc.x); fma2(acc1[2][3], w3.x, vc.x);
                fma2(acc1[3][0], w0.x, vd.x); fma2(acc1[3][1], w1.x, vd.x);
                fma2(acc1[3][2], w2.x, vd.x); fma2(acc1[3][3], w3.x, vd.x);
                fma2(acc1[0][0], w0.y, va.y); fma2(acc1[0][1], w1.y, va.y);
                fma2(acc1[0][2], w2.y, va.y); fma2(acc1[0][3], w3.y, va.y);
                fma2(acc1[1][0], w0.y, vb.y); fma2(acc1[1][1], w1.y, vb.y);
                fma2(acc1[1][2], w2.y, vb.y); fma2(acc1[1][3], w3.y, vb.y);
                fma2(acc1[2][0], w0.y, vc.y); fma2(acc1[2][1], w1.y, vc.y);
                fma2(acc1[2][2], w2.y, vc.y); fma2(acc1[2][3], w3.y, vc.y);
                fma2(acc1[3][0], w0.y, vd.y); fma2(acc1[3][1], w1.y, vd.y);
                fma2(acc1[3][2], w2.y, vd.y); fma2(acc1[3][3], w3.y, vd.y);
            }
        }

        // ---- epilogue: h = relu(sum + (1+deg)*u) ----
        #pragma unroll
        for (int r = 0; r < ROWS_PER_WARP; r++) {
            int row = rbase + r;
            if (row < n) {
                float sc = has_u ? (1.f + (float)deg[row]) : 0.f;
                float2 p0 = unpack2(acc1[r][0]);
                float2 p1 = unpack2(acc1[r][1]);
                float2 p2 = unpack2(acc1[r][2]);
                float2 p3 = unpack2(acc1[r][3]);
                *(float4*)(xout + (size_t)row * 128 + lane * 4) = make_float4(
                    fmaxf(p0.x + p0.y + sc * uu[0], 0.f),
                    fmaxf(p1.x + p1.y + sc * uu[1], 0.f),
                    fmaxf(p2.x + p2.y + sc * uu[2], 0.f),
                    fmaxf(p3.x + p3.y + sc * uu[3], 0.f));
            }
        }
        __syncwarp();   // rows_w reads done before next chunk's staging
    }
}

// ================= pooling + folded final GEMM =================
__device__ __forceinline__ int lower_bound_i(const int* __restrict__ a, int lo, int hi, int v) {
    while (lo < hi) {
        int m = (lo + hi) >> 1;
        if (a[m] < v) lo = m + 1; else hi = m;
    }
    return lo;
}

__global__ void pool_kernel(float* __restrict__ pool, int* __restrict__ cnt,
                            const float* __restrict__ hf,
                            const int* __restrict__ batch, int n) {
    const int g = blockIdx.x;
    const int j = threadIdx.x;
    int lo = lower_bound_i(batch, 0, n, g);
    int hi = lower_bound_i(batch, lo, n, g + 1);
    float s0 = 0.f, s1 = 0.f, s2 = 0.f, s3 = 0.f;
    int r = lo;
    for (; r + 4 <= hi; r += 4) {
        s0 += hf[(size_t)(r + 0) * D + j];
        s1 += hf[(size_t)(r + 1) * D + j];
        s2 += hf[(size_t)(r + 2) * D + j];
        s3 += hf[(size_t)(r + 3) * D + j];
    }
    for (; r < hi; r++) s0 += hf[(size_t)r * D + j];
    pool[(size_t)g * D + j] = (s0 + s1) + (s2 + s3);
    if (j == 0) cnt[g] = hi - lo;
}

__global__ void finish_kernel(float* __restrict__ out,
                              const float* __restrict__ pool, const int* __restrict__ cnt,
                              const float* __restrict__ W2, const float* __restrict__ b2) {
    __shared__ float P[D];
    const int g = blockIdx.x;
    const int c = threadIdx.x;
    P[c] = pool[(size_t)g * D + c];
    __syncthreads();
    float s = (float)cnt[g] * b2[c];
    #pragma unroll 8
    for (int k = 0; k < D; k++) s += P[k] * W2[k * D + c];
    out[(size_t)g * D + c] = s;
}

// ================= launch =================
extern "C" void kernel_launch(void* const* d_in, const int* in_sizes, int n_in,
                              void* d_out, int out_size) {
    const float* x   = (const float*)d_in[0];
    const float* W1  = (const float*)d_in[1];
    const float* b1  = (const float*)d_in[2];
    const float* W2  = (const float*)d_in[3];
    const float* b2  = (const float*)d_in[4];
    const int* ei    = (const int*)d_in[5];
    const int* bat   = (const int*)d_in[6];
    float* out       = (float*)d_out;

    const int N = in_sizes[0] / D;
    const int E = in_sizes[5] / 2;
    const int n_layers = in_sizes[1] / (D * D);
    const int n_graphs = out_size / D;

    float *acc, *xA, *xB, *pool, *W12, *uvec;
    int *counts, *offs, *cursor, *csr, *cnt;
    cudaGetSymbolAddress((void**)&acc, g_acc);
    cudaGetSymbolAddress((void**)&xA, g_xA);
    cudaGetSymbolAddress((void**)&xB, g_xB);
    cudaGetSymbolAddress((void**)&counts, g_counts);
    cudaGetSymbolAddress((void**)&offs, g_offs);
    cudaGetSymbolAddress((void**)&cursor, g_cursor);
    cudaGetSymbolAddress((void**)&csr, g_csr_src);
    cudaGetSymbolAddress((void**)&pool, g_pool);
    cudaGetSymbolAddress((void**)&cnt, g_cnt);
    cudaGetSymbolAddress((void**)&W12, g_W12);
    cudaGetSymbolAddress((void**)&uvec, g_u);

    const int smem_bytes = (16384 + MLP_WARPS * ROWS_PER_WARP * 128) * 4;  // 90112
    cudaFuncSetAttribute(mlp_single_kernel, cudaFuncAttributeMaxDynamicSharedMemorySize, smem_bytes);

    // ---- CSR build ----
    cudaMemsetAsync(counts, 0, (size_t)N * sizeof(int), 0);
    hist_kernel<<<(E + 255) / 256, 256>>>(ei, E, counts);
    scan_kernel<<<1, 1024>>>(counts, N, E, offs, cursor);
    fill_kernel<<<(E + 255) / 256, 256>>>(ei, E, cursor, csr);

    // ---- fused-weight precompute: W12_l = W2_l @ W1_{l+1}, u_l = b2_l @ W1_{l+1} ----
    for (int l = 0; l + 1 < n_layers; l++) {
        wmul_kernel<<<D + 1, D>>>(W12 + (size_t)l * D * D, uvec + (size_t)l * D,
                                  W2 + (size_t)l * D * D, W1 + (size_t)(l + 1) * D * D,
                                  b2 + (size_t)l * D);
    }

    // ---- layers: gather + single fused GEMM each ----
    const int nchunks = (N + ROWS_PER_WARP - 1) / ROWS_PER_WARP;
    const int gather_blocks = (N * 32 + 255) / 256;
    const float* xin = x;
    float* bufs[2] = { xA, xB };

    for (int l = 0; l < n_layers; l++) {
        gather_kernel<<<gather_blocks, 256>>>((float4*)acc, (const float4*)xin,
                                              offs, csr, N);
        const float* Wg = (l == 0) ? W1 : (W12 + (size_t)(l - 1) * D * D);
        const float* bg = b1 + (size_t)l * D;
        const float* ug = (l == 0) ? (const float*)nullptr : (uvec + (size_t)(l - 1) * D);
        mlp_single_kernel<<<296, MLP_THREADS, smem_bytes>>>(
            (const float4*)acc, Wg, bg, ug, (l == 0) ? 0 : 1, counts,
            bufs[l & 1], N, nchunks);
        xin = bufs[l & 1];
    }

    // ---- pooled readout + folded final GEMM2 (fp32 exact) ----
    const float* W2l = W2 + (size_t)(n_layers - 1) * D * D;
    const float* b2l = b2 + (size_t)(n_layers - 1) * D;
    pool_kernel<<<n_graphs, D>>>(pool, cnt, xin, bat, N);
    finish_kernel<<<n_graphs, D>>>(out, pool, cnt, W2l, b2l);
}

// round 16
// speedup vs baseline: 4.0004x; 1.0583x over previous
#include <cuda_runtime.h>
#include <cuda_bf16.h>
#include <cstdint>

#define D 128
#define FUSED_THREADS 384
#define FUSED_WARPS 12
#define ROWS_PER_WARP 4

typedef unsigned long long ull;

// -------- scratch (no cudaMalloc allowed) --------
#define MAX_NODES 100000
#define MAX_EDGES 1600000
#define N_GRAPHS_MAX 128
__device__ float g_xA[(size_t)MAX_NODES * D];
__device__ float g_xB[(size_t)MAX_NODES * D];
__device__ int   g_counts[MAX_NODES];
__device__ int   g_offs[MAX_NODES + 1];
__device__ int   g_cursor[MAX_NODES];
__device__ int   g_csr_src[MAX_EDGES];
__device__ float g_pool[N_GRAPHS_MAX * D];
__device__ int   g_cnt[N_GRAPHS_MAX];
__device__ float g_W12[2 * D * D];   // fused W2_l @ W1_{l+1}
__device__ float g_u[2 * D];         // b2_l @ W1_{l+1}

// -------- packed fp32x2 helpers (Blackwell FFMA2) --------
__device__ __forceinline__ ull pack2(float lo, float hi) {
    ull r; asm("mov.b64 %0, {%1,%2};" : "=l"(r) : "f"(lo), "f"(hi)); return r;
}
__device__ __forceinline__ void fma2(ull &d, ull a, ull b) {
    asm("fma.rn.f32x2 %0, %1, %2, %0;" : "+l"(d) : "l"(a), "l"(b));
}
__device__ __forceinline__ float2 unpack2(ull v) {
    float2 f; asm("mov.b64 {%0,%1}, %2;" : "=f"(f.x), "=f"(f.y) : "l"(v)); return f;
}

// ================= CSR build =================
__global__ void hist_kernel(const int* __restrict__ ei, int E, int* __restrict__ counts) {
    int e = blockIdx.x * blockDim.x + threadIdx.x;
    if (e < E) atomicAdd(&counts[ei[(size_t)E + e]], 1);
}

__global__ void scan_kernel(const int* __restrict__ counts, int N, int E,
                            int* __restrict__ offs, int* __restrict__ cursor) {
    __shared__ int sm[1024];
    const int tid = threadIdx.x;
    const int chunk = (N + 1023) / 1024;
    const int lo = tid * chunk;
    const int hi = min(lo + chunk, N);
    int s = 0;
    for (int i = lo; i < hi; i++) s += counts[i];
    sm[tid] = s;
    __syncthreads();
    for (int off = 1; off < 1024; off <<= 1) {
        int t = (tid >= off) ? sm[tid - off] : 0;
        __syncthreads();
        sm[tid] += t;
        __syncthreads();
    }
    int run = sm[tid] - s;
    for (int i = lo; i < hi; i++) {
        int c = counts[i];
        offs[i] = run; cursor[i] = run;
        run += c;
    }
    if (tid == 0) offs[N] = E;
}

__global__ void fill_kernel(const int* __restrict__ ei, int E,
                            int* __restrict__ cursor, int* __restrict__ csr_src) {
    int e = blockIdx.x * blockDim.x + threadIdx.x;
    if (e < E) {
        int d = ei[(size_t)E + e];
        int pos = atomicAdd(&cursor[d], 1);
        csr_src[pos] = ei[e];
    }
}

// ================= fused-weight precompute =================
__global__ void wmul_kernel(float* __restrict__ W12, float* __restrict__ u,
                            const float* __restrict__ W2, const float* __restrict__ W1n,
                            const float* __restrict__ b2) {
    __shared__ float row[D];
    const int k = blockIdx.x;
    const int c = threadIdx.x;
    row[c] = (k < D) ? W2[k * D + c] : b2[c];
    __syncthreads();
    float s = 0.f;
    #pragma unroll 8
    for (int j = 0; j < D; j++) s += row[j] * W1n[j * D + c];
    if (k < D) W12[k * D + c] = s;
    else       u[c] = s;
}

// ================= fused layer: gather + single GEMM =================
// h[v] = relu( (x[v] + sum_in x[u]) @ W + b + (1+deg_v)*u )
// 2 CTAs/SM (384 thr, 88KB SMEM, <=85 regs): 24 warps/SM. Warp-autonomous
// 4-row chunks: gather rows into private SMEM strip, syncwarp, GEMM (proven
// conflict-free XOR-swizzled W), epilogue. Gather latency of one warp is
// covered by the other 23 warps' FFMA2 issue.
__global__ void __launch_bounds__(FUSED_THREADS, 2) fused_layer_kernel(
    const float4* __restrict__ x4,
    const float* __restrict__ W, const float* __restrict__ b,
    const float* __restrict__ u, int has_u,
    const int* __restrict__ offs, const int* __restrict__ csr,
    float* __restrict__ xout, int n, int nchunks)
{
    extern __shared__ float smem[];
    float* Ws   = smem;                           // 16384 floats
    float* rows = Ws + 16384;                     // 12 warps * 4 rows * 128 = 6144

    const int tid  = threadIdx.x;
    const int lane = tid & 31;
    const int wid  = tid >> 5;
    float* rows_w  = rows + wid * (ROWS_PER_WARP * 128);

    // ---- stage W^T with XOR swizzle (conflict-free LDS.128 k-quads) ----
    {
        const float4* wg = (const float4*)W;
        for (int i = tid; i < 4096; i += FUSED_THREADS) {
            int k = i >> 5, c4 = i & 31;
            float4 a = wg[i];
            int kq = k >> 2, kr = k & 3;
            #pragma unroll
            for (int j = 0; j < 4; j++) {
                int c = 4 * c4 + j;
                int addr = c * 128 + 4 * (kq ^ ((c >> 2) & 31)) + kr;
                float av = (j == 0) ? a.x : (j == 1) ? a.y : (j == 2) ? a.z : a.w;
                Ws[addr] = av;
            }
        }
    }
    float bb[4], uu[4];
    #pragma unroll
    for (int j = 0; j < 4; j++) {
        bb[j] = b[lane * 4 + j];
        uu[j] = has_u ? u[lane * 4 + j] : 0.f;
    }
    __syncthreads();   // W visible; only block-wide sync in kernel

    const int warps_total = gridDim.x * FUSED_WARPS;
    for (int c = blockIdx.x * FUSED_WARPS + wid; c < nchunks; c += warps_total) {
        const int rbase = c * ROWS_PER_WARP;

        // ---- gather 4 rows directly into the warp's private SMEM strip ----
        for (int rr = 0; rr < ROWS_PER_WARP; rr++) {
            const int row = rbase + rr;
            float4 a = make_float4(0.f, 0.f, 0.f, 0.f);
            if (row < n) {
                a = x4[(size_t)row * 32 + lane];
                const int lo = offs[row];
                const int hi = offs[row + 1];
                for (int base = lo; base < hi; base += 32) {
                    int cnt = hi - base; if (cnt > 32) cnt = 32;
                    int idx = (lane < cnt) ? __ldg(csr + base + lane) : 0;
                    int j = 0;
                    for (; j + 8 <= cnt; j += 8) {
                        int s0 = __shfl_sync(0xffffffffu, idx, j + 0);
                        int s1 = __shfl_sync(0xffffffffu, idx, j + 1);
                        int s2 = __shfl_sync(0xffffffffu, idx, j + 2);
                        int s3 = __shfl_sync(0xffffffffu, idx, j + 3);
                        int s4 = __shfl_sync(0xffffffffu, idx, j + 4);
                        int s5 = __shfl_sync(0xffffffffu, idx, j + 5);
                        int s6 = __shfl_sync(0xffffffffu, idx, j + 6);
                        int s7 = __shfl_sync(0xffffffffu, idx, j + 7);
                        float4 v0 = __ldg(x4 + (size_t)s0 * 32 + lane);
                        float4 v1 = __ldg(x4 + (size_t)s1 * 32 + lane);
                        float4 v2 = __ldg(x4 + (size_t)s2 * 32 + lane);
                        float4 v3 = __ldg(x4 + (size_t)s3 * 32 + lane);
                        float4 v4 = __ldg(x4 + (size_t)s4 * 32 + lane);
                        float4 v5 = __ldg(x4 + (size_t)s5 * 32 + lane);
                        float4 v6 = __ldg(x4 + (size_t)s6 * 32 + lane);
                        float4 v7 = __ldg(x4 + (size_t)s7 * 32 + lane);
                        a.x += v0.x + v1.x + v2.x + v3.x + v4.x + v5.x + v6.x + v7.x;
                        a.y += v0.y + v1.y + v2.y + v3.y + v4.y + v5.y + v6.y + v7.y;
                        a.z += v0.z + v1.z + v2.z + v3.z + v4.z + v5.z + v6.z + v7.z;
                        a.w += v0.w + v1.w + v2.w + v3.w + v4.w + v5.w + v6.w + v7.w;
                    }
                    for (; j < cnt; j++) {
                        int s = __shfl_sync(0xffffffffu, idx, j);
                        float4 v = __ldg(x4 + (size_t)s * 32 + lane);
                        a.x += v.x; a.y += v.y; a.z += v.z; a.w += v.w;
                    }
                }
            }
            ((float4*)rows_w)[rr * 32 + lane] = a;
        }
        __syncwarp();

        // ---- GEMM: acc1 = rows @ W + b ----
        ull acc1[ROWS_PER_WARP][4];
        #pragma unroll
        for (int r = 0; r < ROWS_PER_WARP; r++)
            #pragma unroll
            for (int j = 0; j < 4; j++) acc1[r][j] = pack2(bb[j], 0.f);
        {
            const float* wb = Ws + (lane * 4) * 128;
            #pragma unroll 4
            for (int kq = 0; kq < 32; kq++) {
                const int ch = (kq ^ lane) << 2;
                ulonglong2 w0 = *(const ulonglong2*)(wb + ch);
                ulonglong2 w1 = *(const ulonglong2*)(wb + 128 + ch);
                ulonglong2 w2 = *(const ulonglong2*)(wb + 256 + ch);
                ulonglong2 w3 = *(const ulonglong2*)(wb + 384 + ch);
                ulonglong2 va = *(const ulonglong2*)(rows_w + 0 * 128 + kq * 4);
                ulonglong2 vb = *(const ulonglong2*)(rows_w + 1 * 128 + kq * 4);
                ulonglong2 vc = *(const ulonglong2*)(rows_w + 2 * 128 + kq * 4);
                ulonglong2 vd = *(const ulonglong2*)(rows_w + 3 * 128 + kq * 4);
                fma2(acc1[0][0], w0.x, va.x); fma2(acc1[0][1], w1.x, va.x);
                fma2(acc1[0][2], w2.x, va.x); fma2(acc1[0][3], w3.x, va.x);
                fma2(acc1[1][0], w0.x, vb.x); fma2(acc1[1][1], w1.x, vb.x);
                fma2(acc1[1][2], w2.x, vb.x); fma2(acc1[1][3], w3.x, vb.x);
                fma2(acc1[2][0], w0.x, vc.x); fma2(acc1[2][1], w1.x, vc.x);
                fma2(acc1[2][2], w2.x, vc.x); fma2(acc1[2][3], w3.x, vc.x);
                fma2(acc1[3][0], w0.x, vd.x); fma2(acc1[3][1], w1.x, vd.x);
                fma2(acc1[3][2], w2.x, vd.x); fma2(acc1[3][3], w3.x, vd.x);
                fma2(acc1[0][0], w0.y, va.y); fma2(acc1[0][1], w1.y, va.y);
                fma2(acc1[0][2], w2.y, va.y); fma2(acc1[0][3], w3.y, va.y);
                fma2(acc1[1][0], w0.y, vb.y); fma2(acc1[1][1], w1.y, vb.y);
                fma2(acc1[1][2], w2.y, vb.y); fma2(acc1[1][3], w3.y, vb.y);
                fma2(acc1[2][0], w0.y, vc.y); fma2(acc1[2][1], w1.y, vc.y);
                fma2(acc1[2][2], w2.y, vc.y); fma2(acc1[2][3], w3.y, vc.y);
                fma2(acc1[3][0], w0.y, vd.y); fma2(acc1[3][1], w1.y, vd.y);
                fma2(acc1[3][2], w2.y, vd.y); fma2(acc1[3][3], w3.y, vd.y);
            }
        }

        // ---- epilogue: h = relu(sum + (1+deg)*u) ----
        #pragma unroll
        for (int r = 0; r < ROWS_PER_WARP; r++) {
            int row = rbase + r;
            if (row < n) {
                float sc = has_u ? (1.f + (float)(offs[row + 1] - offs[row])) : 0.f;
                float2 p0 = unpack2(acc1[r][0]);
                float2 p1 = unpack2(acc1[r][1]);
                float2 p2 = unpack2(acc1[r][2]);
                float2 p3 = unpack2(acc1[r][3]);
                *(float4*)(xout + (size_t)row * 128 + lane * 4) = make_float4(
                    fmaxf(p0.x + p0.y + sc * uu[0], 0.f),
                    fmaxf(p1.x + p1.y + sc * uu[1], 0.f),
                    fmaxf(p2.x + p2.y + sc * uu[2], 0.f),
                    fmaxf(p3.x + p3.y + sc * uu[3], 0.f));
            }
        }
        __syncwarp();   // rows_w reads done before next chunk's gather rewrites
    }
}

// ================= pooling + folded final GEMM =================
__device__ __forceinline__ int lower_bound_i(const int* __restrict__ a, int lo, int hi, int v) {
    while (lo < hi) {
        int m = (lo + hi) >> 1;
        if (a[m] < v) lo = m + 1; else hi = m;
    }
    return lo;
}

__global__ void pool_kernel(float* __restrict__ pool, int* __restrict__ cnt,
                            const float* __restrict__ hf,
                            const int* __restrict__ batch, int n) {
    const int g = blockIdx.x;
    const int j = threadIdx.x;
    int lo = lower_bound_i(batch, 0, n, g);
    int hi = lower_bound_i(batch, lo, n, g + 1);
    float s0 = 0.f, s1 = 0.f, s2 = 0.f, s3 = 0.f;
    int r = lo;
    for (; r + 4 <= hi; r += 4) {
        s0 += hf[(size_t)(r + 0) * D + j];
        s1 += hf[(size_t)(r + 1) * D + j];
        s2 += hf[(size_t)(r + 2) * D + j];
        s3 += hf[(size_t)(r + 3) * D + j];
    }
    for (; r < hi; r++) s0 += hf[(size_t)r * D + j];
    pool[(size_t)g * D + j] = (s0 + s1) + (s2 + s3);
    if (j == 0) cnt[g] = hi - lo;
}

__global__ void finish_kernel(float* __restrict__ out,
                              const float* __restrict__ pool, const int* __restrict__ cnt,
                              const float* __restrict__ W2, const float* __restrict__ b2) {
    __shared__ float P[D];
    const int g = blockIdx.x;
    const int c = threadIdx.x;
    P[c] = pool[(size_t)g * D + c];
    __syncthreads();
    float s = (float)cnt[g] * b2[c];
    #pragma unroll 8
    for (int k = 0; k < D; k++) s += P[k] * W2[k * D + c];
    out[(size_t)g * D + c] = s;
}

// ================= launch =================
extern "C" void kernel_launch(void* const* d_in, const int* in_sizes, int n_in,
                              void* d_out, int out_size) {
    const float* x   = (const float*)d_in[0];
    const float* W1  = (const float*)d_in[1];
    const float* b1  = (const float*)d_in[2];
    const float* W2  = (const float*)d_in[3];
    const float* b2  = (const float*)d_in[4];
    const int* ei    = (const int*)d_in[5];
    const int* bat   = (const int*)d_in[6];
    float* out       = (float*)d_out;

    const int N = in_sizes[0] / D;
    const int E = in_sizes[5] / 2;
    const int n_layers = in_sizes[1] / (D * D);
    const int n_graphs = out_size / D;

    float *xA, *xB, *pool, *W12, *uvec;
    int *counts, *offs, *cursor, *csr, *cnt;
    cudaGetSymbolAddress((void**)&xA, g_xA);
    cudaGetSymbolAddress((void**)&xB, g_xB);
    cudaGetSymbolAddress((void**)&counts, g_counts);
    cudaGetSymbolAddress((void**)&offs, g_offs);
    cudaGetSymbolAddress((void**)&cursor, g_cursor);
    cudaGetSymbolAddress((void**)&csr, g_csr_src);
    cudaGetSymbolAddress((void**)&pool, g_pool);
    cudaGetSymbolAddress((void**)&cnt, g_cnt);
    cudaGetSymbolAddress((void**)&W12, g_W12);
    cudaGetSymbolAddress((void**)&uvec, g_u);

    const int smem_bytes = (16384 + FUSED_WARPS * ROWS_PER_WARP * 128) * 4;  // 90112
    cudaFuncSetAttribute(fused_layer_kernel, cudaFuncAttributeMaxDynamicSharedMemorySize, smem_bytes);

    // ---- CSR build ----
    cudaMemsetAsync(counts, 0, (size_t)N * sizeof(int), 0);
    hist_kernel<<<(E + 255) / 256, 256>>>(ei, E, counts);
    scan_kernel<<<1, 1024>>>(counts, N, E, offs, cursor);
    fill_kernel<<<(E + 255) / 256, 256>>>(ei, E, cursor, csr);

    // ---- fused-weight precompute: W12_l = W2_l @ W1_{l+1}, u_l = b2_l @ W1_{l+1} ----
    for (int l = 0; l + 1 < n_layers; l++) {
        wmul_kernel<<<D + 1, D>>>(W12 + (size_t)l * D * D, uvec + (size_t)l * D,
                                  W2 + (size_t)l * D * D, W1 + (size_t)(l + 1) * D * D,
                                  b2 + (size_t)l * D);
    }

    // ---- layers: one fused gather+GEMM kernel each ----
    const int nchunks = (N + ROWS_PER_WARP - 1) / ROWS_PER_WARP;
    const float* xin = x;
    float* bufs[2] = { xA, xB };

    for (int l = 0; l < n_layers; l++) {
        const float* Wg = (l == 0) ? W1 : (W12 + (size_t)(l - 1) * D * D);
        const float* bg = b1 + (size_t)l * D;
        const float* ug = (l == 0) ? (const float*)nullptr : (uvec + (size_t)(l - 1) * D);
        fused_layer_kernel<<<296, FUSED_THREADS, smem_bytes>>>(
            (const float4*)xin, Wg, bg, ug, (l == 0) ? 0 : 1,
            offs, csr, bufs[l & 1], N, nchunks);
        xin = bufs[l & 1];
    }

    // ---- pooled readout + folded final GEMM2 (fp32 exact) ----
    const float* W2l = W2 + (size_t)(n_layers - 1) * D * D;
    const float* b2l = b2 + (size_t)(n_layers - 1) * D;
    pool_kernel<<<n_graphs, D>>>(pool, cnt, xin, bat, N);
    finish_kernel<<<n_graphs, D>>>(out, pool, cnt, W2l, b2l);
}

// round 17
// speedup vs baseline: 4.1021x; 1.0254x over previous
#include <cuda_runtime.h>
#include <cuda_bf16.h>
#include <cstdint>

#define D 128
#define FUSED_THREADS 384
#define FUSED_WARPS 12
#define ROWS_PER_WARP 4

typedef unsigned long long ull;

// -------- scratch (no cudaMalloc allowed) --------
#define MAX_NODES 100000
#define MAX_EDGES 1600000
#define N_GRAPHS_MAX 128
__device__ float g_xA[(size_t)MAX_NODES * D];
__device__ float g_xB[(size_t)MAX_NODES * D];
__device__ int   g_counts[MAX_NODES];
__device__ int   g_offs[MAX_NODES + 1];
__device__ int   g_cursor[MAX_NODES];
__device__ int   g_csr_src[MAX_EDGES];
__device__ float g_pool[N_GRAPHS_MAX * D];
__device__ int   g_cnt[N_GRAPHS_MAX];
__device__ float g_W12[2 * D * D];   // fused W2_l @ W1_{l+1}
__device__ float g_u[2 * D];         // b2_l @ W1_{l+1}

// -------- packed fp32x2 helpers (Blackwell FFMA2) --------
__device__ __forceinline__ ull pack2(float lo, float hi) {
    ull r; asm("mov.b64 %0, {%1,%2};" : "=l"(r) : "f"(lo), "f"(hi)); return r;
}
__device__ __forceinline__ void fma2(ull &d, ull a, ull b) {
    asm("fma.rn.f32x2 %0, %1, %2, %0;" : "+l"(d) : "l"(a), "l"(b));
}
__device__ __forceinline__ float2 unpack2(ull v) {
    float2 f; asm("mov.b64 {%0,%1}, %2;" : "=f"(f.x), "=f"(f.y) : "l"(v)); return f;
}
__device__ __forceinline__ void add4(float4 &a, const float4 &v) {
    a.x += v.x; a.y += v.y; a.z += v.z; a.w += v.w;
}

// ================= CSR build =================
__global__ void hist_kernel(const int* __restrict__ ei, int E, int* __restrict__ counts) {
    int e = blockIdx.x * blockDim.x + threadIdx.x;
    if (e < E) atomicAdd(&counts[ei[(size_t)E + e]], 1);
}

__global__ void scan_kernel(const int* __restrict__ counts, int N, int E,
                            int* __restrict__ offs, int* __restrict__ cursor) {
    __shared__ int sm[1024];
    const int tid = threadIdx.x;
    const int chunk = (N + 1023) / 1024;
    const int lo = tid * chunk;
    const int hi = min(lo + chunk, N);
    int s = 0;
    for (int i = lo; i < hi; i++) s += counts[i];
    sm[tid] = s;
    __syncthreads();
    for (int off = 1; off < 1024; off <<= 1) {
        int t = (tid >= off) ? sm[tid - off] : 0;
        __syncthreads();
        sm[tid] += t;
        __syncthreads();
    }
    int run = sm[tid] - s;
    for (int i = lo; i < hi; i++) {
        int c = counts[i];
        offs[i] = run; cursor[i] = run;
        run += c;
    }
    if (tid == 0) offs[N] = E;
}

__global__ void fill_kernel(const int* __restrict__ ei, int E,
                            int* __restrict__ cursor, int* __restrict__ csr_src) {
    int e = blockIdx.x * blockDim.x + threadIdx.x;
    if (e < E) {
        int d = ei[(size_t)E + e];
        int pos = atomicAdd(&cursor[d], 1);
        csr_src[pos] = ei[e];
    }
}

// ================= fused-weight precompute (both boundaries in one launch) =================
__global__ void wmul_kernel(float* __restrict__ W12, float* __restrict__ u,
                            const float* __restrict__ W2, const float* __restrict__ W1,
                            const float* __restrict__ b2, int nb) {
    __shared__ float row[D];
    const int l = blockIdx.x / 129;     // boundary index
    const int k = blockIdx.x % 129;
    const int c = threadIdx.x;
    const float* W2l = W2 + (size_t)l * D * D;
    const float* W1n = W1 + (size_t)(l + 1) * D * D;
    row[c] = (k < D) ? W2l[k * D + c] : b2[l * D + c];
    __syncthreads();
    float s = 0.f;
    #pragma unroll 8
    for (int j = 0; j < D; j++) s += row[j] * W1n[j * D + c];
    if (k < D) W12[(size_t)l * D * D + k * D + c] = s;
    else       u[l * D + c] = s;
}

// ================= fused layer: gather + single GEMM =================
// h[v] = relu( (x[v] + sum_in x[u]) @ W + b + (1+deg_v)*u )
// 2 CTAs/SM, 24 warps/SM, warp-autonomous 4-row chunks. Gather uses cross-row
// idx prefetch: offs + first idx batch for all 4 rows issued before any
// accumulation -> the per-row idx->data serial chain is paid once, not 4x.
__global__ void __launch_bounds__(FUSED_THREADS, 2) fused_layer_kernel(
    const float4* __restrict__ x4,
    const float* __restrict__ W, const float* __restrict__ b,
    const float* __restrict__ u, int has_u,
    const int* __restrict__ offs, const int* __restrict__ csr,
    float* __restrict__ xout, int n, int nchunks)
{
    extern __shared__ float smem[];
    float* Ws   = smem;                           // 16384 floats
    float* rows = Ws + 16384;                     // 12 warps * 4 rows * 128 = 6144

    const int tid  = threadIdx.x;
    const int lane = tid & 31;
    const int wid  = tid >> 5;
    float* rows_w  = rows + wid * (ROWS_PER_WARP * 128);

    // ---- stage W^T with XOR swizzle (conflict-free LDS.128 k-quads) ----
    {
        const float4* wg = (const float4*)W;
        for (int i = tid; i < 4096; i += FUSED_THREADS) {
            int k = i >> 5, c4 = i & 31;
            float4 a = wg[i];
            int kq = k >> 2, kr = k & 3;
            #pragma unroll
            for (int j = 0; j < 4; j++) {
                int c = 4 * c4 + j;
                int addr = c * 128 + 4 * (kq ^ ((c >> 2) & 31)) + kr;
                float av = (j == 0) ? a.x : (j == 1) ? a.y : (j == 2) ? a.z : a.w;
                Ws[addr] = av;
            }
        }
    }
    float bb[4], uu[4];
    #pragma unroll
    for (int j = 0; j < 4; j++) {
        bb[j] = b[lane * 4 + j];
        uu[j] = has_u ? u[lane * 4 + j] : 0.f;
    }
    __syncthreads();   // W visible; only block-wide sync in kernel

    const int warps_total = gridDim.x * FUSED_WARPS;
    for (int c = blockIdx.x * FUSED_WARPS + wid; c < nchunks; c += warps_total) {
        const int rbase = c * ROWS_PER_WARP;

        // ---- prefetch phase: offs, self rows, first idx batch for ALL rows ----
        int lo[ROWS_PER_WARP], deg[ROWS_PER_WARP], idx[ROWS_PER_WARP];
        float4 a[ROWS_PER_WARP];
        #pragma unroll
        for (int r = 0; r < ROWS_PER_WARP; r++) {
            int row = rbase + r;
            if (row < n) {
                lo[r]  = __ldg(offs + row);
                deg[r] = __ldg(offs + row + 1) - lo[r];
            } else { lo[r] = 0; deg[r] = 0; }
        }
        #pragma unroll
        for (int r = 0; r < ROWS_PER_WARP; r++) {
            int row = rbase + r;
            a[r] = (row < n) ? __ldg(x4 + (size_t)row * 32 + lane)
                             : make_float4(0.f, 0.f, 0.f, 0.f);
            idx[r] = (lane < deg[r]) ? __ldg(csr + lo[r] + lane) : 0;
        }

        // ---- accumulate each row (idx already in flight) ----
        #pragma unroll
        for (int r = 0; r < ROWS_PER_WARP; r++) {
            int cnt0 = deg[r] < 32 ? deg[r] : 32;
            int j = 0;
            for (; j + 8 <= cnt0; j += 8) {
                int s0 = __shfl_sync(0xffffffffu, idx[r], j + 0);
                int s1 = __shfl_sync(0xffffffffu, idx[r], j + 1);
                int s2 = __shfl_sync(0xffffffffu, idx[r], j + 2);
                int s3 = __shfl_sync(0xffffffffu, idx[r], j + 3);
                int s4 = __shfl_sync(0xffffffffu, idx[r], j + 4);
                int s5 = __shfl_sync(0xffffffffu, idx[r], j + 5);
                int s6 = __shfl_sync(0xffffffffu, idx[r], j + 6);
                int s7 = __shfl_sync(0xffffffffu, idx[r], j + 7);
                float4 v0 = __ldg(x4 + (size_t)s0 * 32 + lane);
                float4 v1 = __ldg(x4 + (size_t)s1 * 32 + lane);
                float4 v2 = __ldg(x4 + (size_t)s2 * 32 + lane);
                float4 v3 = __ldg(x4 + (size_t)s3 * 32 + lane);
                float4 v4 = __ldg(x4 + (size_t)s4 * 32 + lane);
                float4 v5 = __ldg(x4 + (size_t)s5 * 32 + lane);
                float4 v6 = __ldg(x4 + (size_t)s6 * 32 + lane);
                float4 v7 = __ldg(x4 + (size_t)s7 * 32 + lane);
                add4(a[r], v0); add4(a[r], v1); add4(a[r], v2); add4(a[r], v3);
                add4(a[r], v4); add4(a[r], v5); add4(a[r], v6); add4(a[r], v7);
            }
            for (; j < cnt0; j++) {
                int s = __shfl_sync(0xffffffffu, idx[r], j);
                add4(a[r], __ldg(x4 + (size_t)s * 32 + lane));
            }
            // rare overflow: degree > 32
            for (int base = 32; base < deg[r]; base += 32) {
                int cnt = deg[r] - base; if (cnt > 32) cnt = 32;
                int ix = (lane < cnt) ? __ldg(csr + lo[r] + base + lane) : 0;
                for (int q = 0; q < cnt; q++) {
                    int s = __shfl_sync(0xffffffffu, ix, q);
                    add4(a[r], __ldg(x4 + (size_t)s * 32 + lane));
                }
            }
            ((float4*)rows_w)[r * 32 + lane] = a[r];
        }
        __syncwarp();

        // ---- GEMM: acc1 = rows @ W + b ----
        ull acc1[ROWS_PER_WARP][4];
        #pragma unroll
        for (int r = 0; r < ROWS_PER_WARP; r++)
            #pragma unroll
            for (int j = 0; j < 4; j++) acc1[r][j] = pack2(bb[j], 0.f);
        {
            const float* wb = Ws + (lane * 4) * 128;
            #pragma unroll 4
            for (int kq = 0; kq < 32; kq++) {
                const int ch = (kq ^ lane) << 2;
                ulonglong2 w0 = *(const ulonglong2*)(wb + ch);
                ulonglong2 w1 = *(const ulonglong2*)(wb + 128 + ch);
                ulonglong2 w2 = *(const ulonglong2*)(wb + 256 + ch);
                ulonglong2 w3 = *(const ulonglong2*)(wb + 384 + ch);
                ulonglong2 va = *(const ulonglong2*)(rows_w + 0 * 128 + kq * 4);
                ulonglong2 vb = *(const ulonglong2*)(rows_w + 1 * 128 + kq * 4);
                ulonglong2 vc = *(const ulonglong2*)(rows_w + 2 * 128 + kq * 4);
                ulonglong2 vd = *(const ulonglong2*)(rows_w + 3 * 128 + kq * 4);
                fma2(acc1[0][0], w0.x, va.x); fma2(acc1[0][1], w1.x, va.x);
                fma2(acc1[0][2], w2.x, va.x); fma2(acc1[0][3], w3.x, va.x);
                fma2(acc1[1][0], w0.x, vb.x); fma2(acc1[1][1], w1.x, vb.x);
                fma2(acc1[1][2], w2.x, vb.x); fma2(acc1[1][3], w3.x, vb.x);
                fma2(acc1[2][0], w0.x, vc.x); fma2(acc1[2][1], w1.x, vc.x);
                fma2(acc1[2][2], w2.x, vc.x); fma2(acc1[2][3], w3.x, vc.x);
                fma2(acc1[3][0], w0.x, vd.x); fma2(acc1[3][1], w1.x, vd.x);
                fma2(acc1[3][2], w2.x, vd.x); fma2(acc1[3][3], w3.x, vd.x);
                fma2(acc1[0][0], w0.y, va.y); fma2(acc1[0][1], w1.y, va.y);
                fma2(acc1[0][2], w2.y, va.y); fma2(acc1[0][3], w3.y, va.y);
                fma2(acc1[1][0], w0.y, vb.y); fma2(acc1[1][1], w1.y, vb.y);
                fma2(acc1[1][2], w2.y, vb.y); fma2(acc1[1][3], w3.y, vb.y);
                fma2(acc1[2][0], w0.y, vc.y); fma2(acc1[2][1], w1.y, vc.y);
                fma2(acc1[2][2], w2.y, vc.y); fma2(acc1[2][3], w3.y, vc.y);
                fma2(acc1[3][0], w0.y, vd.y); fma2(acc1[3][1], w1.y, vd.y);
                fma2(acc1[3][2], w2.y, vd.y); fma2(acc1[3][3], w3.y, vd.y);
            }
        }

        // ---- epilogue: h = relu(sum + (1+deg)*u) ----
        #pragma unroll
        for (int r = 0; r < ROWS_PER_WARP; r++) {
            int row = rbase + r;
            if (row < n) {
                float sc = has_u ? (1.f + (float)deg[r]) : 0.f;
                float2 p0 = unpack2(acc1[r][0]);
                float2 p1 = unpack2(acc1[r][1]);
                float2 p2 = unpack2(acc1[r][2]);
                float2 p3 = unpack2(acc1[r][3]);
                *(float4*)(xout + (size_t)row * 128 + lane * 4) = make_float4(
                    fmaxf(p0.x + p0.y + sc * uu[0], 0.f),
                    fmaxf(p1.x + p1.y + sc * uu[1], 0.f),
                    fmaxf(p2.x + p2.y + sc * uu[2], 0.f),
                    fmaxf(p3.x + p3.y + sc * uu[3], 0.f));
            }
        }
        __syncwarp();   // rows_w reads done before next chunk's gather rewrites
    }
}

// ================= pooling + folded final GEMM =================
__device__ __forceinline__ int lower_bound_i(const int* __restrict__ a, int lo, int hi, int v) {
    while (lo < hi) {
        int m = (lo + hi) >> 1;
        if (a[m] < v) lo = m + 1; else hi = m;
    }
    return lo;
}

__global__ void pool_kernel(float* __restrict__ pool, int* __restrict__ cnt,
                            const float* __restrict__ hf,
                            const int* __restrict__ batch, int n) {
    const int g = blockIdx.x;
    const int j = threadIdx.x;
    int lo = lower_bound_i(batch, 0, n, g);
    int hi = lower_bound_i(batch, lo, n, g + 1);
    float s0 = 0.f, s1 = 0.f, s2 = 0.f, s3 = 0.f;
    int r = lo;
    for (; r + 4 <= hi; r += 4) {
        s0 += hf[(size_t)(r + 0) * D + j];
        s1 += hf[(size_t)(r + 1) * D + j];
        s2 += hf[(size_t)(r + 2) * D + j];
        s3 += hf[(size_t)(r + 3) * D + j];
    }
    for (; r < hi; r++) s0 += hf[(size_t)r * D + j];
    pool[(size_t)g * D + j] = (s0 + s1) + (s2 + s3);
    if (j == 0) cnt[g] = hi - lo;
}

__global__ void finish_kernel(float* __restrict__ out,
                              const float* __restrict__ pool, const int* __restrict__ cnt,
                              const float* __restrict__ W2, const float* __restrict__ b2) {
    __shared__ float P[D];
    const int g = blockIdx.x;
    const int c = threadIdx.x;
    P[c] = pool[(size_t)g * D + c];
    __syncthreads();
    float s = (float)cnt[g] * b2[c];
    #pragma unroll 8
    for (int k = 0; k < D; k++) s += P[k] * W2[k * D + c];
    out[(size_t)g * D + c] = s;
}

// ================= launch =================
extern "C" void kernel_launch(void* const* d_in, const int* in_sizes, int n_in,
                              void* d_out, int out_size) {
    const float* x   = (const float*)d_in[0];
    const float* W1  = (const float*)d_in[1];
    const float* b1  = (const float*)d_in[2];
    const float* W2  = (const float*)d_in[3];
    const float* b2  = (const float*)d_in[4];
    const int* ei    = (const int*)d_in[5];
    const int* bat   = (const int*)d_in[6];
    float* out       = (float*)d_out;

    const int N = in_sizes[0] / D;
    const int E = in_sizes[5] / 2;
    const int n_layers = in_sizes[1] / (D * D);
    const int n_graphs = out_size / D;

    float *xA, *xB, *pool, *W12, *uvec;
    int *counts, *offs, *cursor, *csr, *cnt;
    cudaGetSymbolAddress((void**)&xA, g_xA);
    cudaGetSymbolAddress((void**)&xB, g_xB);
    cudaGetSymbolAddress((void**)&counts, g_counts);
    cudaGetSymbolAddress((void**)&offs, g_offs);
    cudaGetSymbolAddress((void**)&cursor, g_cursor);
    cudaGetSymbolAddress((void**)&csr, g_csr_src);
    cudaGetSymbolAddress((void**)&pool, g_pool);
    cudaGetSymbolAddress((void**)&cnt, g_cnt);
    cudaGetSymbolAddress((void**)&W12, g_W12);
    cudaGetSymbolAddress((void**)&uvec, g_u);

    const int smem_bytes = (16384 + FUSED_WARPS * ROWS_PER_WARP * 128) * 4;  // 90112
    cudaFuncSetAttribute(fused_layer_kernel, cudaFuncAttributeMaxDynamicSharedMemorySize, smem_bytes);

    // ---- CSR build: launches 1-3 ----
    cudaMemsetAsync(counts, 0, (size_t)N * sizeof(int), 0);
    hist_kernel<<<(E + 255) / 256, 256>>>(ei, E, counts);
    scan_kernel<<<1, 1024>>>(counts, N, E, offs, cursor);
    fill_kernel<<<(E + 255) / 256, 256>>>(ei, E, cursor, csr);

    const int nchunks = (N + ROWS_PER_WARP - 1) / ROWS_PER_WARP;
    const float* xin = x;
    float* bufs[2] = { xA, xB };

    // ---- layer 0: launch 4 (profiled by ncu) ----
    fused_layer_kernel<<<296, FUSED_THREADS, smem_bytes>>>(
        (const float4*)xin, W1, b1, nullptr, 0, offs, csr, bufs[0], N, nchunks);
    xin = bufs[0];

    // ---- fused-weight precompute for layers 1..n-1 (single launch) ----
    const int nb = n_layers - 1;
    if (nb > 0)
        wmul_kernel<<<nb * 129, D>>>(W12, uvec, W2, W1, b2, nb);

    // ---- layers 1..n-1 ----
    for (int l = 1; l < n_layers; l++) {
        fused_layer_kernel<<<296, FUSED_THREADS, smem_bytes>>>(
            (const float4*)xin,
            W12 + (size_t)(l - 1) * D * D, b1 + (size_t)l * D,
            uvec + (size_t)(l - 1) * D, 1,
            offs, csr, bufs[l & 1], N, nchunks);
        xin = bufs[l & 1];
    }

    // ---- pooled readout + folded final GEMM2 (fp32 exact) ----
    const float* W2l = W2 + (size_t)(n_layers - 1) * D * D;
    const float* b2l = b2 + (size_t)(n_layers - 1) * D;
    pool_kernel<<<n_graphs, D>>>(pool, cnt, xin, bat, N);
    finish_kernel<<<n_graphs, D>>>(out, pool, cnt, W2l, b2l);
}